// round 12
// baseline (speedup 1.0000x reference)
#include <cuda_runtime.h>
#include <math.h>

#define NN 100000
#define NE 3200000
#define EPS 1e-5f

// ---------------- scratch (static device globals; no allocation) -------------
__device__ int   g_cnt[NN];               // zero-init at load; k_scan resets each run
__device__ int   g_rowptr[NN + 1];
__device__ int   g_cursor[NN];
__device__ float g_dis[NN];
__device__ float g_sc[NN];
__device__ __align__(16)  int2  g_edge[NE + 8];   // +8 zero padding for vector tails
__device__ __align__(256) float g_T[(size_t)NN * 128];
__device__ __align__(256) float g_A[(size_t)NN * 128];
__device__ __align__(256) float g_B[(size_t)NN * 128];
__device__ float g_t4[NN];

// ---------------- fused gemm1 (x@W1, 128->32, R=2) + degree count -------------
// Dynamic smem: [Ws: 128*32 f32][xs: 64*(128+4) f32]  (x rows 16B-aligned)
__global__ void __launch_bounds__(256) k_gemm1_count(
        const float* __restrict__ in, const float* __restrict__ W,
        float* __restrict__ t,
        const int* __restrict__ dst, int* cnt) {
    constexpr int DIN = 128, DOUT = 32, R = 2;
    constexpr int OX  = DOUT / 4;        // 8
    constexpr int GR  = 256 / OX;        // 32
    constexpr int NPB = GR * R;          // 64
    constexpr int XP  = DIN + 4;
    extern __shared__ float dynsm[];
    float* Ws = dynsm;                                   // 128*32
    float* xs = dynsm + DIN * DOUT;                      // 64*132

    const int tid = threadIdx.x;
    for (int i = tid; i < DIN * DOUT; i += 256) Ws[i] = W[i];
    __syncthreads();

    const int base = blockIdx.x * NPB;
    for (int i = tid; i < NPB * DIN; i += 256) {
        int r = i / DIN, k = i - r * DIN;
        int node = base + r;
        xs[r * XP + k] = (node < NN) ? in[(size_t)node * DIN + k] : 0.0f;
    }
    __syncthreads();

    const int ox = tid % OX;
    const int r0 = (tid / OX) * R;

    float4 acc0 = make_float4(0.f, 0.f, 0.f, 0.f);
    float4 acc1 = make_float4(0.f, 0.f, 0.f, 0.f);
#pragma unroll 4
    for (int k4 = 0; k4 < DIN; k4 += 4) {
        float4 w0 = *reinterpret_cast<const float4*>(&Ws[(k4+0) * DOUT + ox * 4]);
        float4 w1 = *reinterpret_cast<const float4*>(&Ws[(k4+1) * DOUT + ox * 4]);
        float4 w2 = *reinterpret_cast<const float4*>(&Ws[(k4+2) * DOUT + ox * 4]);
        float4 w3 = *reinterpret_cast<const float4*>(&Ws[(k4+3) * DOUT + ox * 4]);
        float4 x0 = *reinterpret_cast<const float4*>(&xs[r0 * XP + k4]);
        float4 x1 = *reinterpret_cast<const float4*>(&xs[(r0 + 1) * XP + k4]);
        acc0.x += x0.x*w0.x + x0.y*w1.x + x0.z*w2.x + x0.w*w3.x;
        acc0.y += x0.x*w0.y + x0.y*w1.y + x0.z*w2.y + x0.w*w3.y;
        acc0.z += x0.x*w0.z + x0.y*w1.z + x0.z*w2.z + x0.w*w3.z;
        acc0.w += x0.x*w0.w + x0.y*w1.w + x0.z*w2.w + x0.w*w3.w;
        acc1.x += x1.x*w0.x + x1.y*w1.x + x1.z*w2.x + x1.w*w3.x;
        acc1.y += x1.x*w0.y + x1.y*w1.y + x1.z*w2.y + x1.w*w3.y;
        acc1.z += x1.x*w0.z + x1.y*w1.z + x1.z*w2.z + x1.w*w3.z;
        acc1.w += x1.x*w0.w + x1.y*w1.w + x1.z*w2.w + x1.w*w3.w;
    }
    if (base + r0 < NN)
        *reinterpret_cast<float4*>(&t[(size_t)(base + r0) * DOUT + ox * 4]) = acc0;
    if (base + r0 + 1 < NN)
        *reinterpret_cast<float4*>(&t[(size_t)(base + r0 + 1) * DOUT + ox * 4]) = acc1;

    const int gtid = blockIdx.x * 256 + tid;
    const int nth  = gridDim.x * 256;
    for (int i = gtid; i < NE / 4; i += nth) {
        int4 d4 = reinterpret_cast<const int4*>(dst)[i];
        atomicAdd(&cnt[d4.x], 1);
        atomicAdd(&cnt[d4.y], 1);
        atomicAdd(&cnt[d4.z], 1);
        atomicAdd(&cnt[d4.w], 1);
    }
}

// single-block scan
__global__ void __launch_bounds__(1024) k_scan(int* cnt, int* rowptr, int* cursor,
                                               float* dis, float* sc) {
    __shared__ int part[1024];
    constexpr int CH = (NN + 1023) / 1024;   // 98
    const int tid = threadIdx.x;
    const int beg = tid * CH;
    const int end = (beg + CH < NN) ? beg + CH : NN;
    int sum = 0;
    for (int i = beg; i < end; ++i) sum += cnt[i];
    part[tid] = sum;
    __syncthreads();
    for (int o = 1; o < 1024; o <<= 1) {
        int v = 0;
        if (tid >= o) v = part[tid - o];
        __syncthreads();
        if (tid >= o) part[tid] += v;
        __syncthreads();
    }
    int run = (tid > 0) ? part[tid - 1] : 0;
    for (int i = beg; i < end; ++i) {
        rowptr[i] = run;
        cursor[i] = run;
        int c = cnt[i];
        cnt[i] = 0;                       // reset for next replay
        run += c;
        float d = (float)(c + 1);
        dis[i] = rsqrtf(d);
        sc[i]  = 1.0f / d;
    }
    if (tid == 1023) rowptr[NN] = part[1023];
}

// permute: 4 edges/thread via int4 loads -> 4 independent atomic+store chains
__global__ void __launch_bounds__(256) k_permute(const int* __restrict__ src,
                                                 const int* __restrict__ dst,
                                                 const float* __restrict__ dis,
                                                 int* cursor, int2* edges) {
    int i = blockIdx.x * blockDim.x + threadIdx.x;
    if (i >= NE / 4) return;
    int4 s4 = reinterpret_cast<const int4*>(src)[i];
    int4 d4 = reinterpret_cast<const int4*>(dst)[i];
    float ds0 = dis[s4.x], dd0 = dis[d4.x];
    float ds1 = dis[s4.y], dd1 = dis[d4.y];
    float ds2 = dis[s4.z], dd2 = dis[d4.z];
    float ds3 = dis[s4.w], dd3 = dis[d4.w];
    int p0 = atomicAdd(&cursor[d4.x], 1);
    int p1 = atomicAdd(&cursor[d4.y], 1);
    int p2 = atomicAdd(&cursor[d4.z], 1);
    int p3 = atomicAdd(&cursor[d4.w], 1);
    edges[p0] = make_int2(s4.x, __float_as_int(ds0 * dd0));
    edges[p1] = make_int2(s4.y, __float_as_int(ds1 * dd1));
    edges[p2] = make_int2(s4.z, __float_as_int(ds2 * dd2));
    edges[p3] = make_int2(s4.w, __float_as_int(ds3 * dd3));
}

// ---------------- GEMM: out = in @ W (+bias+bn+elu if ACT), float4 x loads ----
template<int DIN, int DOUT, int R, bool ACT>
__global__ void __launch_bounds__(256) k_gemm(const float* __restrict__ in,
                       const float* __restrict__ W,
                       const float* __restrict__ b,
                       const float* __restrict__ bg, const float* __restrict__ bbe,
                       const float* __restrict__ bm, const float* __restrict__ bv,
                       float* __restrict__ out) {
    constexpr int OX  = DOUT / 4;
    constexpr int GR  = 256 / OX;
    constexpr int NPB = GR * R;
    constexpr int XP  = DIN + 4;
    __shared__ __align__(16) float Ws[DIN * DOUT];
    __shared__ __align__(16) float xs[NPB][XP];
    __shared__ float sh_scale[DOUT];
    __shared__ float sh_shift[DOUT];

    const int tid = threadIdx.x;
    for (int i = tid; i < DIN * DOUT; i += 256) Ws[i] = W[i];
    if (ACT) {
        if (tid < DOUT) {
            float s = bg[tid] * rsqrtf(bv[tid] + EPS);
            sh_scale[tid] = s;
            sh_shift[tid] = s * (b[tid] - bm[tid]) + bbe[tid];
        }
    }
    __syncthreads();

    const int base = blockIdx.x * NPB;
    for (int i = tid; i < NPB * DIN; i += 256) {
        int r = i / DIN, k = i - r * DIN;
        int node = base + r;
        xs[r][k] = (node < NN) ? in[(size_t)node * DIN + k] : 0.0f;
    }
    __syncthreads();

    const int ox = tid % OX;
    const int r0 = (tid / OX) * R;

    float4 acc[R];
#pragma unroll
    for (int j = 0; j < R; ++j) acc[j] = make_float4(0.f, 0.f, 0.f, 0.f);

#pragma unroll 4
    for (int k4 = 0; k4 < DIN; k4 += 4) {
        float4 w0 = *reinterpret_cast<const float4*>(&Ws[(k4+0) * DOUT + ox * 4]);
        float4 w1 = *reinterpret_cast<const float4*>(&Ws[(k4+1) * DOUT + ox * 4]);
        float4 w2 = *reinterpret_cast<const float4*>(&Ws[(k4+2) * DOUT + ox * 4]);
        float4 w3 = *reinterpret_cast<const float4*>(&Ws[(k4+3) * DOUT + ox * 4]);
#pragma unroll
        for (int j = 0; j < R; ++j) {
            float4 xv = *reinterpret_cast<const float4*>(&xs[r0 + j][k4]);
            acc[j].x += xv.x*w0.x + xv.y*w1.x + xv.z*w2.x + xv.w*w3.x;
            acc[j].y += xv.x*w0.y + xv.y*w1.y + xv.z*w2.y + xv.w*w3.y;
            acc[j].z += xv.x*w0.z + xv.y*w1.z + xv.z*w2.z + xv.w*w3.z;
            acc[j].w += xv.x*w0.w + xv.y*w1.w + xv.z*w2.w + xv.w*w3.w;
        }
    }

    float4 s4, h4;
    if (ACT) {
        s4 = *reinterpret_cast<const float4*>(&sh_scale[ox * 4]);
        h4 = *reinterpret_cast<const float4*>(&sh_shift[ox * 4]);
    }
#pragma unroll
    for (int j = 0; j < R; ++j) {
        int node = base + r0 + j;
        if (node >= NN) continue;
        float4 o = acc[j];
        if (ACT) {
            o.x = o.x * s4.x + h4.x; o.y = o.y * s4.y + h4.y;
            o.z = o.z * s4.z + h4.z; o.w = o.w * s4.w + h4.w;
            o.x = (o.x > 0.f) ? o.x : expm1f(o.x);
            o.y = (o.y > 0.f) ? o.y : expm1f(o.y);
            o.z = (o.z > 0.f) ? o.z : expm1f(o.z);
            o.w = (o.w > 0.f) ? o.w : expm1f(o.w);
        }
        *reinterpret_cast<float4*>(&out[(size_t)node * DOUT + ox * 4]) = o;
    }
}

// ---------------- gemm3 fused with final dot: t4 = elu(bn3(in@W3+b3)) @ W4 ----
__global__ void __launch_bounds__(256) k_gemm3_dot(
        const float* __restrict__ in,
        const float* __restrict__ W,
        const float* __restrict__ b,
        const float* __restrict__ bg, const float* __restrict__ bbe,
        const float* __restrict__ bm, const float* __restrict__ bv,
        const float* __restrict__ W4,
        float* __restrict__ t4) {
    constexpr int DIN = 64, DOUT = 128, R = 4;
    constexpr int OX  = DOUT / 4;        // 32
    constexpr int GR  = 256 / OX;        // 8
    constexpr int NPB = GR * R;          // 32
    constexpr int XP  = DIN + 4;
    __shared__ __align__(16) float Ws[DIN * DOUT];
    __shared__ __align__(16) float xs[NPB][XP];
    __shared__ float sh_scale[DOUT];
    __shared__ float sh_shift[DOUT];
    __shared__ __align__(16) float w4s[DOUT];

    const int tid = threadIdx.x;
    for (int i = tid; i < DIN * DOUT; i += 256) Ws[i] = W[i];
    if (tid < DOUT) {
        float s = bg[tid] * rsqrtf(bv[tid] + EPS);
        sh_scale[tid] = s;
        sh_shift[tid] = s * (b[tid] - bm[tid]) + bbe[tid];
        w4s[tid] = W4[tid];
    }
    __syncthreads();

    const int base = blockIdx.x * NPB;
    for (int i = tid; i < NPB * DIN; i += 256) {
        int r = i / DIN, k = i - r * DIN;
        int node = base + r;
        xs[r][k] = (node < NN) ? in[(size_t)node * DIN + k] : 0.0f;
    }
    __syncthreads();

    const int ox = tid % OX;             // == lane
    const int r0 = (tid / OX) * R;

    float4 acc[R];
#pragma unroll
    for (int j = 0; j < R; ++j) acc[j] = make_float4(0.f, 0.f, 0.f, 0.f);

#pragma unroll 4
    for (int k4 = 0; k4 < DIN; k4 += 4) {
        float4 w0 = *reinterpret_cast<const float4*>(&Ws[(k4+0) * DOUT + ox * 4]);
        float4 w1 = *reinterpret_cast<const float4*>(&Ws[(k4+1) * DOUT + ox * 4]);
        float4 w2 = *reinterpret_cast<const float4*>(&Ws[(k4+2) * DOUT + ox * 4]);
        float4 w3 = *reinterpret_cast<const float4*>(&Ws[(k4+3) * DOUT + ox * 4]);
#pragma unroll
        for (int j = 0; j < R; ++j) {
            float4 xv = *reinterpret_cast<const float4*>(&xs[r0 + j][k4]);
            acc[j].x += xv.x*w0.x + xv.y*w1.x + xv.z*w2.x + xv.w*w3.x;
            acc[j].y += xv.x*w0.y + xv.y*w1.y + xv.z*w2.y + xv.w*w3.y;
            acc[j].z += xv.x*w0.z + xv.y*w1.z + xv.z*w2.z + xv.w*w3.z;
            acc[j].w += xv.x*w0.w + xv.y*w1.w + xv.z*w2.w + xv.w*w3.w;
        }
    }

    const float4 s4 = *reinterpret_cast<const float4*>(&sh_scale[ox * 4]);
    const float4 h4 = *reinterpret_cast<const float4*>(&sh_shift[ox * 4]);
    const float4 w4 = *reinterpret_cast<const float4*>(&w4s[ox * 4]);
#pragma unroll
    for (int j = 0; j < R; ++j) {
        float4 o = acc[j];
        o.x = o.x * s4.x + h4.x; o.y = o.y * s4.y + h4.y;
        o.z = o.z * s4.z + h4.z; o.w = o.w * s4.w + h4.w;
        o.x = (o.x > 0.f) ? o.x : expm1f(o.x);
        o.y = (o.y > 0.f) ? o.y : expm1f(o.y);
        o.z = (o.z > 0.f) ? o.z : expm1f(o.z);
        o.w = (o.w > 0.f) ? o.w : expm1f(o.w);
        float p = o.x * w4.x + o.y * w4.y + o.z * w4.z + o.w * w4.w;
#pragma unroll
        for (int sh = 16; sh > 0; sh >>= 1)
            p += __shfl_xor_sync(0xffffffffu, p, sh);
        int node = base + r0 + j;
        if (ox == 0 && node < NN) t4[node] = p;
    }
}

// ---------------- sub-warp CSR gather: G nodes/warp, 8-edge-deep MLP ----------
template<int DIM, int G, bool ACT>
__global__ void __launch_bounds__(256) k_gatherG(const float* __restrict__ t,
                         const int* __restrict__ rowptr,
                         const int2* __restrict__ edges,
                         const float* __restrict__ sc,
                         const float* __restrict__ b,
                         const float* __restrict__ bg, const float* __restrict__ bbe,
                         const float* __restrict__ bm, const float* __restrict__ bv,
                         float* __restrict__ outp) {
    constexpr int L = 32 / G;          // lanes per node
    static_assert(DIM == L * 4, "each lane owns a float4");
    const int wid  = (blockIdx.x * blockDim.x + threadIdx.x) >> 5;
    const int lane = threadIdx.x & 31;
    const int sub  = lane / L;
    const int sl   = lane % L;
    const int node = wid * G + sub;
    if (node >= NN) return;
    const int beg = rowptr[node], end = rowptr[node + 1];
    const float s = sc[node];
    const int col = sl * 4;

    float4 p_scale, p_shift;
    if (ACT) {
        float ss0 = bg[col+0] * rsqrtf(bv[col+0] + EPS);
        float ss1 = bg[col+1] * rsqrtf(bv[col+1] + EPS);
        float ss2 = bg[col+2] * rsqrtf(bv[col+2] + EPS);
        float ss3 = bg[col+3] * rsqrtf(bv[col+3] + EPS);
        p_scale = make_float4(ss0, ss1, ss2, ss3);
        p_shift = make_float4(ss0 * (b[col+0] - bm[col+0]) + bbe[col+0],
                              ss1 * (b[col+1] - bm[col+1]) + bbe[col+1],
                              ss2 * (b[col+2] - bm[col+2]) + bbe[col+2],
                              ss3 * (b[col+3] - bm[col+3]) + bbe[col+3]);
    }

    float4 a0 = make_float4(0.f, 0.f, 0.f, 0.f);
    float4 a1 = make_float4(0.f, 0.f, 0.f, 0.f);

    int i = beg;
    for (; i + 8 <= end; i += 8) {
        int2 e[8];
#pragma unroll
        for (int u = 0; u < 8; ++u) e[u] = edges[i + u];
        float4 v[8];
#pragma unroll
        for (int u = 0; u < 8; ++u)
            v[u] = *reinterpret_cast<const float4*>(&t[(size_t)e[u].x * DIM + col]);
#pragma unroll
        for (int u = 0; u < 8; ++u) {
            float c = __int_as_float(e[u].y);
            if (u & 1) { a1.x += c*v[u].x; a1.y += c*v[u].y; a1.z += c*v[u].z; a1.w += c*v[u].w; }
            else       { a0.x += c*v[u].x; a0.y += c*v[u].y; a0.z += c*v[u].z; a0.w += c*v[u].w; }
        }
    }
    if (i < end) {
        int2 e[8];
#pragma unroll
        for (int u = 0; u < 8; ++u) e[u] = edges[i + u];
        float4 v[8];
#pragma unroll
        for (int u = 0; u < 8; ++u)
            v[u] = *reinterpret_cast<const float4*>(&t[(size_t)e[u].x * DIM + col]);
#pragma unroll
        for (int u = 0; u < 8; ++u) {
            float c = (i + u < end) ? __int_as_float(e[u].y) : 0.0f;
            if (u & 1) { a1.x += c*v[u].x; a1.y += c*v[u].y; a1.z += c*v[u].z; a1.w += c*v[u].w; }
            else       { a0.x += c*v[u].x; a0.y += c*v[u].y; a0.z += c*v[u].z; a0.w += c*v[u].w; }
        }
    }

    float4 sv = *reinterpret_cast<const float4*>(&t[(size_t)node * DIM + col]);
    float4 o = make_float4(a0.x + a1.x + sv.x * s, a0.y + a1.y + sv.y * s,
                           a0.z + a1.z + sv.z * s, a0.w + a1.w + sv.w * s);
    if (ACT) {
        o.x = o.x * p_scale.x + p_shift.x;
        o.y = o.y * p_scale.y + p_shift.y;
        o.z = o.z * p_scale.z + p_shift.z;
        o.w = o.w * p_scale.w + p_shift.w;
        o.x = (o.x > 0.f) ? o.x : expm1f(o.x);
        o.y = (o.y > 0.f) ? o.y : expm1f(o.y);
        o.z = (o.z > 0.f) ? o.z : expm1f(o.z);
        o.w = (o.w > 0.f) ? o.w : expm1f(o.w);
    }
    *reinterpret_cast<float4*>(&outp[(size_t)node * DIM + col]) = o;
}

__global__ void __launch_bounds__(256) k_gather1_final(const float* __restrict__ t4,
                                const int* __restrict__ rowptr,
                                const int2* __restrict__ edges,
                                const float* __restrict__ sc,
                                const float* __restrict__ b4,
                                float* __restrict__ out) {
    const int warp = (blockIdx.x * blockDim.x + threadIdx.x) >> 5;
    const int lane = threadIdx.x & 31;
    if (warp >= NN) return;
    const int node = warp;
    const int beg = rowptr[node], end = rowptr[node + 1];
    float acc = 0.0f;
    for (int i = beg + lane; i < end; i += 32) {
        int2 e = edges[i];
        acc += __int_as_float(e.y) * t4[e.x];
    }
#pragma unroll
    for (int o = 16; o > 0; o >>= 1) acc += __shfl_xor_sync(0xffffffffu, acc, o);
    if (lane == 0) {
        float x = acc + t4[node] * sc[node] + b4[0];
        x = (x > 0.0f) ? x : expm1f(x);
        out[node] = 1.0f / (1.0f + expf(-x));
    }
}

// ---------------- launch -----------------------------------------------------
extern "C" void kernel_launch(void* const* d_in, const int* in_sizes, int n_in,
                              void* d_out, int out_size) {
    const float* x   = (const float*)d_in[0];
    const int*   src = (const int*)  d_in[1];
    const int*   dst = (const int*)  d_in[2];
    const float* W1 = (const float*)d_in[3];  const float* b1 = (const float*)d_in[4];
    const float* W2 = (const float*)d_in[5];  const float* b2 = (const float*)d_in[6];
    const float* W3 = (const float*)d_in[7];  const float* b3 = (const float*)d_in[8];
    const float* W4 = (const float*)d_in[9];  const float* b4 = (const float*)d_in[10];
    const float* g1 = (const float*)d_in[11]; const float* be1 = (const float*)d_in[12];
    const float* m1 = (const float*)d_in[13]; const float* v1  = (const float*)d_in[14];
    const float* g2 = (const float*)d_in[15]; const float* be2 = (const float*)d_in[16];
    const float* m2 = (const float*)d_in[17]; const float* v2  = (const float*)d_in[18];
    const float* g3 = (const float*)d_in[19]; const float* be3 = (const float*)d_in[20];
    const float* m3 = (const float*)d_in[21]; const float* v3  = (const float*)d_in[22];
    float* out = (float*)d_out;

    void *pcnt, *prp, *pcur, *pdis, *psc, *pedge, *pT, *pA, *pB, *pt4;
    cudaGetSymbolAddress(&pcnt, g_cnt);
    cudaGetSymbolAddress(&prp,  g_rowptr);
    cudaGetSymbolAddress(&pcur, g_cursor);
    cudaGetSymbolAddress(&pdis, g_dis);
    cudaGetSymbolAddress(&psc,  g_sc);
    cudaGetSymbolAddress(&pedge, g_edge);
    cudaGetSymbolAddress(&pT, g_T);
    cudaGetSymbolAddress(&pA, g_A);
    cudaGetSymbolAddress(&pB, g_B);
    cudaGetSymbolAddress(&pt4, g_t4);
    int* cnt = (int*)pcnt; int* rowptr = (int*)prp; int* cursor = (int*)pcur;
    float* dis = (float*)pdis; float* sc = (float*)psc;
    int2* edges = (int2*)pedge;
    float* T = (float*)pT; float* A = (float*)pA; float* B = (float*)pB;
    float* t4 = (float*)pt4;

    const int TB = 256;
    const int gE4 = (NE / 4 + TB - 1) / TB;
    const int gW = (NN + 7) / 8;                 // warp-per-node kernels
    const int gW4 = (NN + 4 * 8 - 1) / (4 * 8);  // G=4 sub-warp gather (dim 32)
    const int gW2 = (NN + 2 * 8 - 1) / (2 * 8);  // G=2 sub-warp gather (dim 64)

    const int SM1 = 128*32*4 + 64*(128+4)*4;   // 50176 bytes dynamic smem
    cudaFuncSetAttribute((const void*)k_gemm1_count,
                         cudaFuncAttributeMaxDynamicSharedMemorySize, SM1);

    // (1) gemm1 (x@W1 -> T) fused with degree count
    k_gemm1_count<<<(NN + 63) / 64, TB, SM1>>>(x, W1, T, dst, cnt);
    // (2) scan, (3) permute
    k_scan<<<1, 1024>>>(cnt, rowptr, cursor, dis, sc);
    k_permute<<<gE4, TB>>>(src, dst, dis, cursor, edges);

    // (4) layer 1 gather dim32 (G=4) + bias+bn1+elu -> H2   [profiled control]
    k_gatherG<32, 4, true><<<gW4, TB>>>(T, rowptr, edges, sc, b1, g1, be1, m1, v1, A);

    // layer 2: aggregate H2 (dim32, G=4); H3 = elu(bn2(AH2@W2 + b2))
    k_gatherG<32, 4, false><<<gW4, TB>>>(A, rowptr, edges, sc,
                                    nullptr, nullptr, nullptr, nullptr, nullptr, B);
    k_gemm<32, 64, 4, true><<<(NN + 63) / 64, TB>>>(B, W2, b2, g2, be2, m2, v2, T);

    // layer 3: aggregate H3 (dim64, G=2); gemm3 fused with W4 dot -> t4
    k_gatherG<64, 2, false><<<gW2, TB>>>(T, rowptr, edges, sc,
                                    nullptr, nullptr, nullptr, nullptr, nullptr, A);
    k_gemm3_dot<<<(NN + 31) / 32, TB>>>(A, W3, b3, g3, be3, m3, v3, W4, t4);

    // layer 4 final gather + elu + sigmoid
    k_gather1_final<<<gW, TB>>>(t4, rowptr, edges, sc, b4, out);
}

// round 13
// speedup vs baseline: 1.8667x; 1.8667x over previous
#include <cuda_runtime.h>
#include <math.h>

#define NN 100000
#define NE 3200000
#define EPS 1e-5f

// ---------------- scratch (static device globals; no allocation) -------------
__device__ int   g_cnt[NN];               // zero-init at load; scan_apply resets each run
__device__ int   g_part[128];             // per-block partial sums for the scan
__device__ int   g_rowptr[NN + 1];
__device__ int   g_cursor[NN];
__device__ float g_dis[NN];
__device__ float g_sc[NN];
__device__ __align__(16)  int2  g_edge[NE + 8];   // +8 zero padding for vector tails
__device__ __align__(256) float g_T[(size_t)NN * 128];
__device__ __align__(256) float g_A[(size_t)NN * 128];
__device__ __align__(256) float g_B[(size_t)NN * 128];
__device__ float g_t4[NN];

// ---------------- fused gemm1 (x@W1, 128->32, R=2) + degree count -------------
// Dynamic smem: [Ws: 128*32 f32][xs: 64*(128+1) f32]
__global__ void __launch_bounds__(256) k_gemm1_count(
        const float* __restrict__ in, const float* __restrict__ W,
        float* __restrict__ t,
        const int* __restrict__ dst, int* cnt) {
    constexpr int DIN = 128, DOUT = 32, R = 2;
    constexpr int OX  = DOUT / 4;        // 8
    constexpr int GR  = 256 / OX;        // 32
    constexpr int NPB = GR * R;          // 64
    constexpr int XP  = DIN + 1;
    extern __shared__ float dynsm[];
    float* Ws = dynsm;                                   // 128*32
    float* xs = dynsm + DIN * DOUT;                      // 64*129

    const int tid = threadIdx.x;
    for (int i = tid; i < DIN * DOUT; i += 256) Ws[i] = W[i];
    __syncthreads();

    const int base = blockIdx.x * NPB;
    for (int i = tid; i < NPB * DIN; i += 256) {
        int r = i / DIN, k = i - r * DIN;
        int node = base + r;
        xs[r * XP + k] = (node < NN) ? in[(size_t)node * DIN + k] : 0.0f;
    }
    __syncthreads();

    const int ox = tid % OX;
    const int r0 = (tid / OX) * R;

    float4 acc0 = make_float4(0.f, 0.f, 0.f, 0.f);
    float4 acc1 = make_float4(0.f, 0.f, 0.f, 0.f);
#pragma unroll 4
    for (int k = 0; k < DIN; ++k) {
        float4 w = *reinterpret_cast<const float4*>(&Ws[k * DOUT + ox * 4]);
        float x0 = xs[r0 * XP + k];
        float x1 = xs[(r0 + 1) * XP + k];
        acc0.x += x0 * w.x; acc0.y += x0 * w.y; acc0.z += x0 * w.z; acc0.w += x0 * w.w;
        acc1.x += x1 * w.x; acc1.y += x1 * w.y; acc1.z += x1 * w.z; acc1.w += x1 * w.w;
    }
    if (base + r0 < NN)
        *reinterpret_cast<float4*>(&t[(size_t)(base + r0) * DOUT + ox * 4]) = acc0;
    if (base + r0 + 1 < NN)
        *reinterpret_cast<float4*>(&t[(size_t)(base + r0 + 1) * DOUT + ox * 4]) = acc1;

    const int gtid = blockIdx.x * 256 + tid;
    const int nth  = gridDim.x * 256;
    for (int i = gtid; i < NE / 4; i += nth) {
        int4 d4 = reinterpret_cast<const int4*>(dst)[i];
        atomicAdd(&cnt[d4.x], 1);
        atomicAdd(&cnt[d4.y], 1);
        atomicAdd(&cnt[d4.z], 1);
        atomicAdd(&cnt[d4.w], 1);
    }
}

// ---------------- multi-block scan (2 kernels) --------------------------------
// phase 1: per-block partial sums of cnt
__global__ void __launch_bounds__(1024) k_scan_part(const int* __restrict__ cnt,
                                                    int* partials) {
    __shared__ int sh[1024];
    int i = blockIdx.x * 1024 + threadIdx.x;
    sh[threadIdx.x] = (i < NN) ? cnt[i] : 0;
    __syncthreads();
    for (int o = 512; o > 0; o >>= 1) {
        if (threadIdx.x < o) sh[threadIdx.x] += sh[threadIdx.x + o];
        __syncthreads();
    }
    if (threadIdx.x == 0) partials[blockIdx.x] = sh[0];
}

// phase 2: prefix partials in-block, block-wide scan, write CSR + norm coefs,
// reset cnt for next replay.
__global__ void __launch_bounds__(1024) k_scan_apply(int* cnt,
        const int* __restrict__ partials,
        int* rowptr, int* cursor, float* dis, float* sc) {
    constexpr int NBLK = (NN + 1023) / 1024;   // 98
    __shared__ int sp[128];
    __shared__ int sh[1024];
    const int b = blockIdx.x, t = threadIdx.x;
    if (t < 128) sp[t] = (t < NBLK) ? partials[t] : 0;
    __syncthreads();
    for (int o = 1; o < 128; o <<= 1) {
        int v = 0;
        if (t < 128 && t >= o) v = sp[t - o];
        __syncthreads();
        if (t < 128 && t >= o) sp[t] += v;
        __syncthreads();
    }
    const int base = (b > 0) ? sp[b - 1] : 0;
    const int i = b * 1024 + t;
    const int c = (i < NN) ? cnt[i] : 0;
    sh[t] = c;
    __syncthreads();
    for (int o = 1; o < 1024; o <<= 1) {
        int v = 0;
        if (t >= o) v = sh[t - o];
        __syncthreads();
        if (t >= o) sh[t] += v;
        __syncthreads();
    }
    if (i < NN) {
        int pos = base + sh[t] - c;            // exclusive prefix
        rowptr[i] = pos;
        cursor[i] = pos;
        cnt[i] = 0;
        float d = (float)(c + 1);
        dis[i] = rsqrtf(d);
        sc[i]  = 1.0f / d;
    }
    if (b == 0 && t == 0) rowptr[NN] = sp[NBLK - 1];
}

// ---------------- permute (scalar, R10 form) ----------------------------------
__global__ void __launch_bounds__(256) k_permute(const int* __restrict__ src,
                                                 const int* __restrict__ dst,
                                                 const float* __restrict__ dis,
                                                 int* cursor, int2* edges) {
    int e = blockIdx.x * blockDim.x + threadIdx.x;
    if (e >= NE) return;
    int s = src[e], d = dst[e];
    int pos = atomicAdd(&cursor[d], 1);
    edges[pos] = make_int2(s, __float_as_int(dis[s] * dis[d]));
}

// ---------------- GEMM (R10 form): out = in @ W (+bias+bn+elu if ACT) ---------
template<int DIN, int DOUT, int R, bool ACT>
__global__ void __launch_bounds__(256) k_gemm(const float* __restrict__ in,
                       const float* __restrict__ W,
                       const float* __restrict__ b,
                       const float* __restrict__ bg, const float* __restrict__ bbe,
                       const float* __restrict__ bm, const float* __restrict__ bv,
                       float* __restrict__ out) {
    constexpr int OX  = DOUT / 4;
    constexpr int GR  = 256 / OX;
    constexpr int NPB = GR * R;
    __shared__ __align__(16) float Ws[DIN * DOUT];
    __shared__ float xs[NPB][DIN + 1];
    __shared__ float sh_scale[DOUT];
    __shared__ float sh_shift[DOUT];

    const int tid = threadIdx.x;
    for (int i = tid; i < DIN * DOUT; i += 256) Ws[i] = W[i];
    if (ACT) {
        if (tid < DOUT) {
            float s = bg[tid] * rsqrtf(bv[tid] + EPS);
            sh_scale[tid] = s;
            sh_shift[tid] = s * (b[tid] - bm[tid]) + bbe[tid];
        }
    }
    __syncthreads();

    const int base = blockIdx.x * NPB;
    for (int i = tid; i < NPB * DIN; i += 256) {
        int r = i / DIN, k = i - r * DIN;
        int node = base + r;
        xs[r][k] = (node < NN) ? in[(size_t)node * DIN + k] : 0.0f;
    }
    __syncthreads();

    const int ox = tid % OX;
    const int r0 = (tid / OX) * R;

    float4 acc[R];
#pragma unroll
    for (int j = 0; j < R; ++j) acc[j] = make_float4(0.f, 0.f, 0.f, 0.f);

#pragma unroll 4
    for (int k = 0; k < DIN; ++k) {
        float4 w = *reinterpret_cast<const float4*>(&Ws[k * DOUT + ox * 4]);
#pragma unroll
        for (int j = 0; j < R; ++j) {
            float xv = xs[r0 + j][k];
            acc[j].x += xv * w.x; acc[j].y += xv * w.y;
            acc[j].z += xv * w.z; acc[j].w += xv * w.w;
        }
    }

    float4 s4, h4;
    if (ACT) {
        s4 = *reinterpret_cast<const float4*>(&sh_scale[ox * 4]);
        h4 = *reinterpret_cast<const float4*>(&sh_shift[ox * 4]);
    }
#pragma unroll
    for (int j = 0; j < R; ++j) {
        int node = base + r0 + j;
        if (node >= NN) continue;
        float4 o = acc[j];
        if (ACT) {
            o.x = o.x * s4.x + h4.x; o.y = o.y * s4.y + h4.y;
            o.z = o.z * s4.z + h4.z; o.w = o.w * s4.w + h4.w;
            o.x = (o.x > 0.f) ? o.x : expm1f(o.x);
            o.y = (o.y > 0.f) ? o.y : expm1f(o.y);
            o.z = (o.z > 0.f) ? o.z : expm1f(o.z);
            o.w = (o.w > 0.f) ? o.w : expm1f(o.w);
        }
        *reinterpret_cast<float4*>(&out[(size_t)node * DOUT + ox * 4]) = o;
    }
}

// ---------------- gemm3 fused with final dot (R10 form) -----------------------
__global__ void __launch_bounds__(256) k_gemm3_dot(
        const float* __restrict__ in,
        const float* __restrict__ W,
        const float* __restrict__ b,
        const float* __restrict__ bg, const float* __restrict__ bbe,
        const float* __restrict__ bm, const float* __restrict__ bv,
        const float* __restrict__ W4,
        float* __restrict__ t4) {
    constexpr int DIN = 64, DOUT = 128, R = 4;
    constexpr int OX  = DOUT / 4;        // 32
    constexpr int GR  = 256 / OX;        // 8
    constexpr int NPB = GR * R;          // 32
    __shared__ __align__(16) float Ws[DIN * DOUT];
    __shared__ float xs[NPB][DIN + 1];
    __shared__ float sh_scale[DOUT];
    __shared__ float sh_shift[DOUT];
    __shared__ __align__(16) float w4s[DOUT];

    const int tid = threadIdx.x;
    for (int i = tid; i < DIN * DOUT; i += 256) Ws[i] = W[i];
    if (tid < DOUT) {
        float s = bg[tid] * rsqrtf(bv[tid] + EPS);
        sh_scale[tid] = s;
        sh_shift[tid] = s * (b[tid] - bm[tid]) + bbe[tid];
        w4s[tid] = W4[tid];
    }
    __syncthreads();

    const int base = blockIdx.x * NPB;
    for (int i = tid; i < NPB * DIN; i += 256) {
        int r = i / DIN, k = i - r * DIN;
        int node = base + r;
        xs[r][k] = (node < NN) ? in[(size_t)node * DIN + k] : 0.0f;
    }
    __syncthreads();

    const int ox = tid % OX;             // == lane
    const int r0 = (tid / OX) * R;

    float4 acc[R];
#pragma unroll
    for (int j = 0; j < R; ++j) acc[j] = make_float4(0.f, 0.f, 0.f, 0.f);

#pragma unroll 4
    for (int k = 0; k < DIN; ++k) {
        float4 w = *reinterpret_cast<const float4*>(&Ws[k * DOUT + ox * 4]);
#pragma unroll
        for (int j = 0; j < R; ++j) {
            float xv = xs[r0 + j][k];
            acc[j].x += xv * w.x; acc[j].y += xv * w.y;
            acc[j].z += xv * w.z; acc[j].w += xv * w.w;
        }
    }

    const float4 s4 = *reinterpret_cast<const float4*>(&sh_scale[ox * 4]);
    const float4 h4 = *reinterpret_cast<const float4*>(&sh_shift[ox * 4]);
    const float4 w4 = *reinterpret_cast<const float4*>(&w4s[ox * 4]);
#pragma unroll
    for (int j = 0; j < R; ++j) {
        float4 o = acc[j];
        o.x = o.x * s4.x + h4.x; o.y = o.y * s4.y + h4.y;
        o.z = o.z * s4.z + h4.z; o.w = o.w * s4.w + h4.w;
        o.x = (o.x > 0.f) ? o.x : expm1f(o.x);
        o.y = (o.y > 0.f) ? o.y : expm1f(o.y);
        o.z = (o.z > 0.f) ? o.z : expm1f(o.z);
        o.w = (o.w > 0.f) ? o.w : expm1f(o.w);
        float p = o.x * w4.x + o.y * w4.y + o.z * w4.z + o.w * w4.w;
#pragma unroll
        for (int sh = 16; sh > 0; sh >>= 1)
            p += __shfl_xor_sync(0xffffffffu, p, sh);
        int node = base + r0 + j;
        if (ox == 0 && node < NN) t4[node] = p;
    }
}

// ---------------- sub-warp CSR gather (R10 form) ------------------------------
template<int DIM, int G, bool ACT>
__global__ void __launch_bounds__(256) k_gatherG(const float* __restrict__ t,
                         const int* __restrict__ rowptr,
                         const int2* __restrict__ edges,
                         const float* __restrict__ sc,
                         const float* __restrict__ b,
                         const float* __restrict__ bg, const float* __restrict__ bbe,
                         const float* __restrict__ bm, const float* __restrict__ bv,
                         float* __restrict__ outp) {
    constexpr int L = 32 / G;          // lanes per node
    static_assert(DIM == L * 4, "each lane owns a float4");
    const int wid  = (blockIdx.x * blockDim.x + threadIdx.x) >> 5;
    const int lane = threadIdx.x & 31;
    const int sub  = lane / L;
    const int sl   = lane % L;
    const int node = wid * G + sub;
    if (node >= NN) return;
    const int beg = rowptr[node], end = rowptr[node + 1];
    const float s = sc[node];
    const int col = sl * 4;

    float4 p_scale, p_shift;
    if (ACT) {
        float ss0 = bg[col+0] * rsqrtf(bv[col+0] + EPS);
        float ss1 = bg[col+1] * rsqrtf(bv[col+1] + EPS);
        float ss2 = bg[col+2] * rsqrtf(bv[col+2] + EPS);
        float ss3 = bg[col+3] * rsqrtf(bv[col+3] + EPS);
        p_scale = make_float4(ss0, ss1, ss2, ss3);
        p_shift = make_float4(ss0 * (b[col+0] - bm[col+0]) + bbe[col+0],
                              ss1 * (b[col+1] - bm[col+1]) + bbe[col+1],
                              ss2 * (b[col+2] - bm[col+2]) + bbe[col+2],
                              ss3 * (b[col+3] - bm[col+3]) + bbe[col+3]);
    }

    float4 a0 = make_float4(0.f, 0.f, 0.f, 0.f);
    float4 a1 = make_float4(0.f, 0.f, 0.f, 0.f);

    int i = beg;
    for (; i + 8 <= end; i += 8) {
        int2 e[8];
#pragma unroll
        for (int u = 0; u < 8; ++u) e[u] = edges[i + u];
        float4 v[8];
#pragma unroll
        for (int u = 0; u < 8; ++u)
            v[u] = *reinterpret_cast<const float4*>(&t[(size_t)e[u].x * DIM + col]);
#pragma unroll
        for (int u = 0; u < 8; ++u) {
            float c = __int_as_float(e[u].y);
            if (u & 1) { a1.x += c*v[u].x; a1.y += c*v[u].y; a1.z += c*v[u].z; a1.w += c*v[u].w; }
            else       { a0.x += c*v[u].x; a0.y += c*v[u].y; a0.z += c*v[u].z; a0.w += c*v[u].w; }
        }
    }
    if (i < end) {
        int2 e[8];
#pragma unroll
        for (int u = 0; u < 8; ++u) e[u] = edges[i + u];
        float4 v[8];
#pragma unroll
        for (int u = 0; u < 8; ++u)
            v[u] = *reinterpret_cast<const float4*>(&t[(size_t)e[u].x * DIM + col]);
#pragma unroll
        for (int u = 0; u < 8; ++u) {
            float c = (i + u < end) ? __int_as_float(e[u].y) : 0.0f;
            if (u & 1) { a1.x += c*v[u].x; a1.y += c*v[u].y; a1.z += c*v[u].z; a1.w += c*v[u].w; }
            else       { a0.x += c*v[u].x; a0.y += c*v[u].y; a0.z += c*v[u].z; a0.w += c*v[u].w; }
        }
    }

    float4 sv = *reinterpret_cast<const float4*>(&t[(size_t)node * DIM + col]);
    float4 o = make_float4(a0.x + a1.x + sv.x * s, a0.y + a1.y + sv.y * s,
                           a0.z + a1.z + sv.z * s, a0.w + a1.w + sv.w * s);
    if (ACT) {
        o.x = o.x * p_scale.x + p_shift.x;
        o.y = o.y * p_scale.y + p_shift.y;
        o.z = o.z * p_scale.z + p_shift.z;
        o.w = o.w * p_scale.w + p_shift.w;
        o.x = (o.x > 0.f) ? o.x : expm1f(o.x);
        o.y = (o.y > 0.f) ? o.y : expm1f(o.y);
        o.z = (o.z > 0.f) ? o.z : expm1f(o.z);
        o.w = (o.w > 0.f) ? o.w : expm1f(o.w);
    }
    *reinterpret_cast<float4*>(&outp[(size_t)node * DIM + col]) = o;
}

__global__ void __launch_bounds__(256) k_gather1_final(const float* __restrict__ t4,
                                const int* __restrict__ rowptr,
                                const int2* __restrict__ edges,
                                const float* __restrict__ sc,
                                const float* __restrict__ b4,
                                float* __restrict__ out) {
    const int warp = (blockIdx.x * blockDim.x + threadIdx.x) >> 5;
    const int lane = threadIdx.x & 31;
    if (warp >= NN) return;
    const int node = warp;
    const int beg = rowptr[node], end = rowptr[node + 1];
    float acc = 0.0f;
    for (int i = beg + lane; i < end; i += 32) {
        int2 e = edges[i];
        acc += __int_as_float(e.y) * t4[e.x];
    }
#pragma unroll
    for (int o = 16; o > 0; o >>= 1) acc += __shfl_xor_sync(0xffffffffu, acc, o);
    if (lane == 0) {
        float x = acc + t4[node] * sc[node] + b4[0];
        x = (x > 0.0f) ? x : expm1f(x);
        out[node] = 1.0f / (1.0f + expf(-x));
    }
}

// ---------------- launch -----------------------------------------------------
extern "C" void kernel_launch(void* const* d_in, const int* in_sizes, int n_in,
                              void* d_out, int out_size) {
    const float* x   = (const float*)d_in[0];
    const int*   src = (const int*)  d_in[1];
    const int*   dst = (const int*)  d_in[2];
    const float* W1 = (const float*)d_in[3];  const float* b1 = (const float*)d_in[4];
    const float* W2 = (const float*)d_in[5];  const float* b2 = (const float*)d_in[6];
    const float* W3 = (const float*)d_in[7];  const float* b3 = (const float*)d_in[8];
    const float* W4 = (const float*)d_in[9];  const float* b4 = (const float*)d_in[10];
    const float* g1 = (const float*)d_in[11]; const float* be1 = (const float*)d_in[12];
    const float* m1 = (const float*)d_in[13]; const float* v1  = (const float*)d_in[14];
    const float* g2 = (const float*)d_in[15]; const float* be2 = (const float*)d_in[16];
    const float* m2 = (const float*)d_in[17]; const float* v2  = (const float*)d_in[18];
    const float* g3 = (const float*)d_in[19]; const float* be3 = (const float*)d_in[20];
    const float* m3 = (const float*)d_in[21]; const float* v3  = (const float*)d_in[22];
    float* out = (float*)d_out;

    void *pcnt, *ppart, *prp, *pcur, *pdis, *psc, *pedge, *pT, *pA, *pB, *pt4;
    cudaGetSymbolAddress(&pcnt, g_cnt);
    cudaGetSymbolAddress(&ppart, g_part);
    cudaGetSymbolAddress(&prp,  g_rowptr);
    cudaGetSymbolAddress(&pcur, g_cursor);
    cudaGetSymbolAddress(&pdis, g_dis);
    cudaGetSymbolAddress(&psc,  g_sc);
    cudaGetSymbolAddress(&pedge, g_edge);
    cudaGetSymbolAddress(&pT, g_T);
    cudaGetSymbolAddress(&pA, g_A);
    cudaGetSymbolAddress(&pB, g_B);
    cudaGetSymbolAddress(&pt4, g_t4);
    int* cnt = (int*)pcnt; int* part = (int*)ppart;
    int* rowptr = (int*)prp; int* cursor = (int*)pcur;
    float* dis = (float*)pdis; float* sc = (float*)psc;
    int2* edges = (int2*)pedge;
    float* T = (float*)pT; float* A = (float*)pA; float* B = (float*)pB;
    float* t4 = (float*)pt4;

    const int TB = 256;
    const int gE = (NE + TB - 1) / TB;
    const int gW = (NN + 7) / 8;                 // warp-per-node kernels
    const int gW4 = (NN + 4 * 8 - 1) / (4 * 8);  // G=4 sub-warp gather (dim 32)
    const int gW2 = (NN + 2 * 8 - 1) / (2 * 8);  // G=2 sub-warp gather (dim 64)
    const int NBLK = (NN + 1023) / 1024;         // 98 scan blocks

    const int SM1 = 128*32*4 + 64*129*4;   // 49408 bytes dynamic smem for gemm1
    cudaFuncSetAttribute((const void*)k_gemm1_count,
                         cudaFuncAttributeMaxDynamicSharedMemorySize, SM1);

    // (1) gemm1 (x@W1 -> T) fused with degree count
    k_gemm1_count<<<(NN + 63) / 64, TB, SM1>>>(x, W1, T, dst, cnt);
    // (2,3) multi-block scan
    k_scan_part<<<NBLK, 1024>>>(cnt, part);
    k_scan_apply<<<NBLK, 1024>>>(cnt, part, rowptr, cursor, dis, sc);
    // (4) permute  [profiled slot]
    k_permute<<<gE, TB>>>(src, dst, dis, cursor, edges);

    // layer 1 gather dim32 (G=4) + bias+bn1+elu -> H2
    k_gatherG<32, 4, true><<<gW4, TB>>>(T, rowptr, edges, sc, b1, g1, be1, m1, v1, A);

    // layer 2: aggregate H2 (dim32, G=4); H3 = elu(bn2(AH2@W2 + b2))
    k_gatherG<32, 4, false><<<gW4, TB>>>(A, rowptr, edges, sc,
                                    nullptr, nullptr, nullptr, nullptr, nullptr, B);
    k_gemm<32, 64, 4, true><<<(NN + 63) / 64, TB>>>(B, W2, b2, g2, be2, m2, v2, T);

    // layer 3: aggregate H3 (dim64, G=2); gemm3 fused with W4 dot -> t4
    k_gatherG<64, 2, false><<<gW2, TB>>>(T, rowptr, edges, sc,
                                    nullptr, nullptr, nullptr, nullptr, nullptr, A);
    k_gemm3_dot<<<(NN + 31) / 32, TB>>>(A, W3, b3, g3, be3, m3, v3, W4, t4);

    // layer 4 final gather + elu + sigmoid
    k_gather1_final<<<gW, TB>>>(t4, rowptr, edges, sc, b4, out);
}

// round 14
// speedup vs baseline: 1.8745x; 1.0042x over previous
#include <cuda_runtime.h>
#include <math.h>

#define NN 100000
#define NE 3200000
#define EPS 1e-5f

// ---------------- scratch (static device globals; no allocation) -------------
__device__ int   g_cnt[NN];               // zero-init at load; scan_apply resets each run
__device__ int   g_part[128];             // per-block partial sums for the scan
__device__ int   g_rowptr[NN + 1];
__device__ int   g_cursor[NN];
__device__ float g_dis[NN];
__device__ float g_sc[NN];
__device__ __align__(16)  int2  g_edge[NE + 8];   // +8 zero padding for vector tails
__device__ __align__(256) float g_T[(size_t)NN * 128];
__device__ __align__(256) float g_A[(size_t)NN * 128];
__device__ __align__(256) float g_B[(size_t)NN * 128];
__device__ float g_t4[NN];

// ---------------- fused gemm1 (x@W1, 128->32, R=2) + degree count -------------
// Dynamic smem: [Ws: 128*32 f32][xs: 64*(128+1) f32]
__global__ void __launch_bounds__(256) k_gemm1_count(
        const float* __restrict__ in, const float* __restrict__ W,
        float* __restrict__ t,
        const int* __restrict__ dst, int* cnt) {
    constexpr int DIN = 128, DOUT = 32, R = 2;
    constexpr int OX  = DOUT / 4;        // 8
    constexpr int GR  = 256 / OX;        // 32
    constexpr int NPB = GR * R;          // 64
    constexpr int XP  = DIN + 1;
    extern __shared__ float dynsm[];
    float* Ws = dynsm;                                   // 128*32
    float* xs = dynsm + DIN * DOUT;                      // 64*129

    const int tid = threadIdx.x;
    for (int i = tid; i < DIN * DOUT; i += 256) Ws[i] = W[i];
    __syncthreads();

    const int base = blockIdx.x * NPB;
    for (int i = tid; i < NPB * DIN; i += 256) {
        int r = i / DIN, k = i - r * DIN;
        int node = base + r;
        xs[r * XP + k] = (node < NN) ? in[(size_t)node * DIN + k] : 0.0f;
    }
    __syncthreads();

    const int ox = tid % OX;
    const int r0 = (tid / OX) * R;

    float4 acc0 = make_float4(0.f, 0.f, 0.f, 0.f);
    float4 acc1 = make_float4(0.f, 0.f, 0.f, 0.f);
#pragma unroll 4
    for (int k = 0; k < DIN; ++k) {
        float4 w = *reinterpret_cast<const float4*>(&Ws[k * DOUT + ox * 4]);
        float x0 = xs[r0 * XP + k];
        float x1 = xs[(r0 + 1) * XP + k];
        acc0.x += x0 * w.x; acc0.y += x0 * w.y; acc0.z += x0 * w.z; acc0.w += x0 * w.w;
        acc1.x += x1 * w.x; acc1.y += x1 * w.y; acc1.z += x1 * w.z; acc1.w += x1 * w.w;
    }
    if (base + r0 < NN)
        *reinterpret_cast<float4*>(&t[(size_t)(base + r0) * DOUT + ox * 4]) = acc0;
    if (base + r0 + 1 < NN)
        *reinterpret_cast<float4*>(&t[(size_t)(base + r0 + 1) * DOUT + ox * 4]) = acc1;

    const int gtid = blockIdx.x * 256 + tid;
    const int nth  = gridDim.x * 256;
    for (int i = gtid; i < NE / 4; i += nth) {
        int4 d4 = reinterpret_cast<const int4*>(dst)[i];
        atomicAdd(&cnt[d4.x], 1);
        atomicAdd(&cnt[d4.y], 1);
        atomicAdd(&cnt[d4.z], 1);
        atomicAdd(&cnt[d4.w], 1);
    }
}

// ---------------- multi-block scan (2 kernels) --------------------------------
__global__ void __launch_bounds__(1024) k_scan_part(const int* __restrict__ cnt,
                                                    int* partials) {
    __shared__ int sh[1024];
    int i = blockIdx.x * 1024 + threadIdx.x;
    sh[threadIdx.x] = (i < NN) ? cnt[i] : 0;
    __syncthreads();
    for (int o = 512; o > 0; o >>= 1) {
        if (threadIdx.x < o) sh[threadIdx.x] += sh[threadIdx.x + o];
        __syncthreads();
    }
    if (threadIdx.x == 0) partials[blockIdx.x] = sh[0];
}

__global__ void __launch_bounds__(1024) k_scan_apply(int* cnt,
        const int* __restrict__ partials,
        int* rowptr, int* cursor, float* dis, float* sc) {
    constexpr int NBLK = (NN + 1023) / 1024;   // 98
    __shared__ int sp[128];
    __shared__ int sh[1024];
    const int b = blockIdx.x, t = threadIdx.x;
    if (t < 128) sp[t] = (t < NBLK) ? partials[t] : 0;
    __syncthreads();
    for (int o = 1; o < 128; o <<= 1) {
        int v = 0;
        if (t < 128 && t >= o) v = sp[t - o];
        __syncthreads();
        if (t < 128 && t >= o) sp[t] += v;
        __syncthreads();
    }
    const int base = (b > 0) ? sp[b - 1] : 0;
    const int i = b * 1024 + t;
    const int c = (i < NN) ? cnt[i] : 0;
    sh[t] = c;
    __syncthreads();
    for (int o = 1; o < 1024; o <<= 1) {
        int v = 0;
        if (t >= o) v = sh[t - o];
        __syncthreads();
        if (t >= o) sh[t] += v;
        __syncthreads();
    }
    if (i < NN) {
        int pos = base + sh[t] - c;            // exclusive prefix
        rowptr[i] = pos;
        cursor[i] = pos;
        cnt[i] = 0;
        float d = (float)(c + 1);
        dis[i] = rsqrtf(d);
        sc[i]  = 1.0f / d;
    }
    if (b == 0 && t == 0) rowptr[NN] = sp[NBLK - 1];
}

// ---------------- permute (scalar) --------------------------------------------
__global__ void __launch_bounds__(256) k_permute(const int* __restrict__ src,
                                                 const int* __restrict__ dst,
                                                 const float* __restrict__ dis,
                                                 int* cursor, int2* edges) {
    int e = blockIdx.x * blockDim.x + threadIdx.x;
    if (e >= NE) return;
    int s = src[e], d = dst[e];
    int pos = atomicAdd(&cursor[d], 1);
    edges[pos] = make_int2(s, __float_as_int(dis[s] * dis[d]));
}

// ---------------- GEMM: out = in @ W (+bias+bn+elu if ACT) --------------------
template<int DIN, int DOUT, int R, bool ACT>
__global__ void __launch_bounds__(256) k_gemm(const float* __restrict__ in,
                       const float* __restrict__ W,
                       const float* __restrict__ b,
                       const float* __restrict__ bg, const float* __restrict__ bbe,
                       const float* __restrict__ bm, const float* __restrict__ bv,
                       float* __restrict__ out) {
    constexpr int OX  = DOUT / 4;
    constexpr int GR  = 256 / OX;
    constexpr int NPB = GR * R;
    __shared__ __align__(16) float Ws[DIN * DOUT];
    __shared__ float xs[NPB][DIN + 1];
    __shared__ float sh_scale[DOUT];
    __shared__ float sh_shift[DOUT];

    const int tid = threadIdx.x;
    for (int i = tid; i < DIN * DOUT; i += 256) Ws[i] = W[i];
    if (ACT) {
        if (tid < DOUT) {
            float s = bg[tid] * rsqrtf(bv[tid] + EPS);
            sh_scale[tid] = s;
            sh_shift[tid] = s * (b[tid] - bm[tid]) + bbe[tid];
        }
    }
    __syncthreads();

    const int base = blockIdx.x * NPB;
    for (int i = tid; i < NPB * DIN; i += 256) {
        int r = i / DIN, k = i - r * DIN;
        int node = base + r;
        xs[r][k] = (node < NN) ? in[(size_t)node * DIN + k] : 0.0f;
    }
    __syncthreads();

    const int ox = tid % OX;
    const int r0 = (tid / OX) * R;

    float4 acc[R];
#pragma unroll
    for (int j = 0; j < R; ++j) acc[j] = make_float4(0.f, 0.f, 0.f, 0.f);

#pragma unroll 4
    for (int k = 0; k < DIN; ++k) {
        float4 w = *reinterpret_cast<const float4*>(&Ws[k * DOUT + ox * 4]);
#pragma unroll
        for (int j = 0; j < R; ++j) {
            float xv = xs[r0 + j][k];
            acc[j].x += xv * w.x; acc[j].y += xv * w.y;
            acc[j].z += xv * w.z; acc[j].w += xv * w.w;
        }
    }

    float4 s4, h4;
    if (ACT) {
        s4 = *reinterpret_cast<const float4*>(&sh_scale[ox * 4]);
        h4 = *reinterpret_cast<const float4*>(&sh_shift[ox * 4]);
    }
#pragma unroll
    for (int j = 0; j < R; ++j) {
        int node = base + r0 + j;
        if (node >= NN) continue;
        float4 o = acc[j];
        if (ACT) {
            o.x = o.x * s4.x + h4.x; o.y = o.y * s4.y + h4.y;
            o.z = o.z * s4.z + h4.z; o.w = o.w * s4.w + h4.w;
            o.x = (o.x > 0.f) ? o.x : expm1f(o.x);
            o.y = (o.y > 0.f) ? o.y : expm1f(o.y);
            o.z = (o.z > 0.f) ? o.z : expm1f(o.z);
            o.w = (o.w > 0.f) ? o.w : expm1f(o.w);
        }
        *reinterpret_cast<float4*>(&out[(size_t)node * DOUT + ox * 4]) = o;
    }
}

// ---------------- gemm3 fused with final dot ----------------------------------
__global__ void __launch_bounds__(256) k_gemm3_dot(
        const float* __restrict__ in,
        const float* __restrict__ W,
        const float* __restrict__ b,
        const float* __restrict__ bg, const float* __restrict__ bbe,
        const float* __restrict__ bm, const float* __restrict__ bv,
        const float* __restrict__ W4,
        float* __restrict__ t4) {
    constexpr int DIN = 64, DOUT = 128, R = 4;
    constexpr int OX  = DOUT / 4;        // 32
    constexpr int GR  = 256 / OX;        // 8
    constexpr int NPB = GR * R;          // 32
    __shared__ __align__(16) float Ws[DIN * DOUT];
    __shared__ float xs[NPB][DIN + 1];
    __shared__ float sh_scale[DOUT];
    __shared__ float sh_shift[DOUT];
    __shared__ __align__(16) float w4s[DOUT];

    const int tid = threadIdx.x;
    for (int i = tid; i < DIN * DOUT; i += 256) Ws[i] = W[i];
    if (tid < DOUT) {
        float s = bg[tid] * rsqrtf(bv[tid] + EPS);
        sh_scale[tid] = s;
        sh_shift[tid] = s * (b[tid] - bm[tid]) + bbe[tid];
        w4s[tid] = W4[tid];
    }
    __syncthreads();

    const int base = blockIdx.x * NPB;
    for (int i = tid; i < NPB * DIN; i += 256) {
        int r = i / DIN, k = i - r * DIN;
        int node = base + r;
        xs[r][k] = (node < NN) ? in[(size_t)node * DIN + k] : 0.0f;
    }
    __syncthreads();

    const int ox = tid % OX;             // == lane
    const int r0 = (tid / OX) * R;

    float4 acc[R];
#pragma unroll
    for (int j = 0; j < R; ++j) acc[j] = make_float4(0.f, 0.f, 0.f, 0.f);

#pragma unroll 4
    for (int k = 0; k < DIN; ++k) {
        float4 w = *reinterpret_cast<const float4*>(&Ws[k * DOUT + ox * 4]);
#pragma unroll
        for (int j = 0; j < R; ++j) {
            float xv = xs[r0 + j][k];
            acc[j].x += xv * w.x; acc[j].y += xv * w.y;
            acc[j].z += xv * w.z; acc[j].w += xv * w.w;
        }
    }

    const float4 s4 = *reinterpret_cast<const float4*>(&sh_scale[ox * 4]);
    const float4 h4 = *reinterpret_cast<const float4*>(&sh_shift[ox * 4]);
    const float4 w4 = *reinterpret_cast<const float4*>(&w4s[ox * 4]);
#pragma unroll
    for (int j = 0; j < R; ++j) {
        float4 o = acc[j];
        o.x = o.x * s4.x + h4.x; o.y = o.y * s4.y + h4.y;
        o.z = o.z * s4.z + h4.z; o.w = o.w * s4.w + h4.w;
        o.x = (o.x > 0.f) ? o.x : expm1f(o.x);
        o.y = (o.y > 0.f) ? o.y : expm1f(o.y);
        o.z = (o.z > 0.f) ? o.z : expm1f(o.z);
        o.w = (o.w > 0.f) ? o.w : expm1f(o.w);
        float p = o.x * w4.x + o.y * w4.y + o.z * w4.z + o.w * w4.w;
#pragma unroll
        for (int sh = 16; sh > 0; sh >>= 1)
            p += __shfl_xor_sync(0xffffffffu, p, sh);
        int node = base + r0 + j;
        if (ox == 0 && node < NN) t4[node] = p;
    }
}

// ---------------- sub-warp CSR gather: G nodes/warp, UN=4, high occupancy -----
template<int DIM, int G, bool ACT>
__global__ void __launch_bounds__(256, 6) k_gatherG(const float* __restrict__ t,
                         const int* __restrict__ rowptr,
                         const int2* __restrict__ edges,
                         const float* __restrict__ sc,
                         const float* __restrict__ b,
                         const float* __restrict__ bg, const float* __restrict__ bbe,
                         const float* __restrict__ bm, const float* __restrict__ bv,
                         float* __restrict__ outp) {
    constexpr int L = 32 / G;          // lanes per node
    static_assert(DIM == L * 4, "each lane owns a float4");
    const int wid  = (blockIdx.x * blockDim.x + threadIdx.x) >> 5;
    const int lane = threadIdx.x & 31;
    const int sub  = lane / L;
    const int sl   = lane % L;
    const int node = wid * G + sub;
    if (node >= NN) return;
    const int beg = rowptr[node], end = rowptr[node + 1];
    const float s = sc[node];
    const int col = sl * 4;

    float4 p_scale, p_shift;
    if (ACT) {
        float ss0 = bg[col+0] * rsqrtf(bv[col+0] + EPS);
        float ss1 = bg[col+1] * rsqrtf(bv[col+1] + EPS);
        float ss2 = bg[col+2] * rsqrtf(bv[col+2] + EPS);
        float ss3 = bg[col+3] * rsqrtf(bv[col+3] + EPS);
        p_scale = make_float4(ss0, ss1, ss2, ss3);
        p_shift = make_float4(ss0 * (b[col+0] - bm[col+0]) + bbe[col+0],
                              ss1 * (b[col+1] - bm[col+1]) + bbe[col+1],
                              ss2 * (b[col+2] - bm[col+2]) + bbe[col+2],
                              ss3 * (b[col+3] - bm[col+3]) + bbe[col+3]);
    }

    float4 a0 = make_float4(0.f, 0.f, 0.f, 0.f);
    float4 a1 = make_float4(0.f, 0.f, 0.f, 0.f);

    int i = beg;
    for (; i + 4 <= end; i += 4) {
        int2 e0 = edges[i],   e1 = edges[i+1];
        int2 e2 = edges[i+2], e3 = edges[i+3];
        float4 v0 = *reinterpret_cast<const float4*>(&t[(size_t)e0.x * DIM + col]);
        float4 v1 = *reinterpret_cast<const float4*>(&t[(size_t)e1.x * DIM + col]);
        float4 v2 = *reinterpret_cast<const float4*>(&t[(size_t)e2.x * DIM + col]);
        float4 v3 = *reinterpret_cast<const float4*>(&t[(size_t)e3.x * DIM + col]);
        float c0 = __int_as_float(e0.y), c1 = __int_as_float(e1.y);
        float c2 = __int_as_float(e2.y), c3 = __int_as_float(e3.y);
        a0.x += c0*v0.x; a0.y += c0*v0.y; a0.z += c0*v0.z; a0.w += c0*v0.w;
        a1.x += c1*v1.x; a1.y += c1*v1.y; a1.z += c1*v1.z; a1.w += c1*v1.w;
        a0.x += c2*v2.x; a0.y += c2*v2.y; a0.z += c2*v2.z; a0.w += c2*v2.w;
        a1.x += c3*v3.x; a1.y += c3*v3.y; a1.z += c3*v3.z; a1.w += c3*v3.w;
    }
    if (i < end) {
        // predicated 4-wide tail; edges[] has +8 zero padding so loads are safe
        int2 e0 = edges[i],   e1 = edges[i+1];
        int2 e2 = edges[i+2], e3 = edges[i+3];
        float4 v0 = *reinterpret_cast<const float4*>(&t[(size_t)e0.x * DIM + col]);
        float4 v1 = *reinterpret_cast<const float4*>(&t[(size_t)e1.x * DIM + col]);
        float4 v2 = *reinterpret_cast<const float4*>(&t[(size_t)e2.x * DIM + col]);
        float4 v3 = *reinterpret_cast<const float4*>(&t[(size_t)e3.x * DIM + col]);
        float c0 = __int_as_float(e0.y);
        float c1 = (i + 1 < end) ? __int_as_float(e1.y) : 0.0f;
        float c2 = (i + 2 < end) ? __int_as_float(e2.y) : 0.0f;
        float c3 = (i + 3 < end) ? __int_as_float(e3.y) : 0.0f;
        a0.x += c0*v0.x; a0.y += c0*v0.y; a0.z += c0*v0.z; a0.w += c0*v0.w;
        a1.x += c1*v1.x; a1.y += c1*v1.y; a1.z += c1*v1.z; a1.w += c1*v1.w;
        a0.x += c2*v2.x; a0.y += c2*v2.y; a0.z += c2*v2.z; a0.w += c2*v2.w;
        a1.x += c3*v3.x; a1.y += c3*v3.y; a1.z += c3*v3.z; a1.w += c3*v3.w;
    }

    float4 sv = *reinterpret_cast<const float4*>(&t[(size_t)node * DIM + col]);
    float4 o = make_float4(a0.x + a1.x + sv.x * s, a0.y + a1.y + sv.y * s,
                           a0.z + a1.z + sv.z * s, a0.w + a1.w + sv.w * s);
    if (ACT) {
        o.x = o.x * p_scale.x + p_shift.x;
        o.y = o.y * p_scale.y + p_shift.y;
        o.z = o.z * p_scale.z + p_shift.z;
        o.w = o.w * p_scale.w + p_shift.w;
        o.x = (o.x > 0.f) ? o.x : expm1f(o.x);
        o.y = (o.y > 0.f) ? o.y : expm1f(o.y);
        o.z = (o.z > 0.f) ? o.z : expm1f(o.z);
        o.w = (o.w > 0.f) ? o.w : expm1f(o.w);
    }
    *reinterpret_cast<float4*>(&outp[(size_t)node * DIM + col]) = o;
}

__global__ void __launch_bounds__(256) k_gather1_final(const float* __restrict__ t4,
                                const int* __restrict__ rowptr,
                                const int2* __restrict__ edges,
                                const float* __restrict__ sc,
                                const float* __restrict__ b4,
                                float* __restrict__ out) {
    const int warp = (blockIdx.x * blockDim.x + threadIdx.x) >> 5;
    const int lane = threadIdx.x & 31;
    if (warp >= NN) return;
    const int node = warp;
    const int beg = rowptr[node], end = rowptr[node + 1];
    float acc = 0.0f;
    for (int i = beg + lane; i < end; i += 32) {
        int2 e = edges[i];
        acc += __int_as_float(e.y) * t4[e.x];
    }
#pragma unroll
    for (int o = 16; o > 0; o >>= 1) acc += __shfl_xor_sync(0xffffffffu, acc, o);
    if (lane == 0) {
        float x = acc + t4[node] * sc[node] + b4[0];
        x = (x > 0.0f) ? x : expm1f(x);
        out[node] = 1.0f / (1.0f + expf(-x));
    }
}

// ---------------- launch -----------------------------------------------------
extern "C" void kernel_launch(void* const* d_in, const int* in_sizes, int n_in,
                              void* d_out, int out_size) {
    const float* x   = (const float*)d_in[0];
    const int*   src = (const int*)  d_in[1];
    const int*   dst = (const int*)  d_in[2];
    const float* W1 = (const float*)d_in[3];  const float* b1 = (const float*)d_in[4];
    const float* W2 = (const float*)d_in[5];  const float* b2 = (const float*)d_in[6];
    const float* W3 = (const float*)d_in[7];  const float* b3 = (const float*)d_in[8];
    const float* W4 = (const float*)d_in[9];  const float* b4 = (const float*)d_in[10];
    const float* g1 = (const float*)d_in[11]; const float* be1 = (const float*)d_in[12];
    const float* m1 = (const float*)d_in[13]; const float* v1  = (const float*)d_in[14];
    const float* g2 = (const float*)d_in[15]; const float* be2 = (const float*)d_in[16];
    const float* m2 = (const float*)d_in[17]; const float* v2  = (const float*)d_in[18];
    const float* g3 = (const float*)d_in[19]; const float* be3 = (const float*)d_in[20];
    const float* m3 = (const float*)d_in[21]; const float* v3  = (const float*)d_in[22];
    float* out = (float*)d_out;

    void *pcnt, *ppart, *prp, *pcur, *pdis, *psc, *pedge, *pT, *pA, *pB, *pt4;
    cudaGetSymbolAddress(&pcnt, g_cnt);
    cudaGetSymbolAddress(&ppart, g_part);
    cudaGetSymbolAddress(&prp,  g_rowptr);
    cudaGetSymbolAddress(&pcur, g_cursor);
    cudaGetSymbolAddress(&pdis, g_dis);
    cudaGetSymbolAddress(&psc,  g_sc);
    cudaGetSymbolAddress(&pedge, g_edge);
    cudaGetSymbolAddress(&pT, g_T);
    cudaGetSymbolAddress(&pA, g_A);
    cudaGetSymbolAddress(&pB, g_B);
    cudaGetSymbolAddress(&pt4, g_t4);
    int* cnt = (int*)pcnt; int* part = (int*)ppart;
    int* rowptr = (int*)prp; int* cursor = (int*)pcur;
    float* dis = (float*)pdis; float* sc = (float*)psc;
    int2* edges = (int2*)pedge;
    float* T = (float*)pT; float* A = (float*)pA; float* B = (float*)pB;
    float* t4 = (float*)pt4;

    const int TB = 256;
    const int gE = (NE + TB - 1) / TB;
    const int gW = (NN + 7) / 8;                 // warp-per-node kernels
    const int gW4 = (NN + 4 * 8 - 1) / (4 * 8);  // G=4 sub-warp gather (dim 32)
    const int gW2 = (NN + 2 * 8 - 1) / (2 * 8);  // G=2 sub-warp gather (dim 64)
    const int NBLK = (NN + 1023) / 1024;         // 98 scan blocks

    const int SM1 = 128*32*4 + 64*129*4;   // 49408 bytes dynamic smem for gemm1
    cudaFuncSetAttribute((const void*)k_gemm1_count,
                         cudaFuncAttributeMaxDynamicSharedMemorySize, SM1);

    // (1) gemm1 (x@W1 -> T) fused with degree count
    k_gemm1_count<<<(NN + 63) / 64, TB, SM1>>>(x, W1, T, dst, cnt);
    // (2,3) multi-block scan
    k_scan_part<<<NBLK, 1024>>>(cnt, part);
    k_scan_apply<<<NBLK, 1024>>>(cnt, part, rowptr, cursor, dis, sc);
    // (4) permute  [profiled control]
    k_permute<<<gE, TB>>>(src, dst, dis, cursor, edges);

    // layer 1 gather dim32 (G=4) + bias+bn1+elu -> H2
    k_gatherG<32, 4, true><<<gW4, TB>>>(T, rowptr, edges, sc, b1, g1, be1, m1, v1, A);

    // layer 2: aggregate H2 (dim32, G=4); H3 = elu(bn2(AH2@W2 + b2))
    k_gatherG<32, 4, false><<<gW4, TB>>>(A, rowptr, edges, sc,
                                    nullptr, nullptr, nullptr, nullptr, nullptr, B);
    k_gemm<32, 64, 4, true><<<(NN + 63) / 64, TB>>>(B, W2, b2, g2, be2, m2, v2, T);

    // layer 3: aggregate H3 (dim64, G=2); gemm3 fused with W4 dot -> t4
    k_gatherG<64, 2, false><<<gW2, TB>>>(T, rowptr, edges, sc,
                                    nullptr, nullptr, nullptr, nullptr, nullptr, A);
    k_gemm3_dot<<<(NN + 31) / 32, TB>>>(A, W3, b3, g3, be3, m3, v3, W4, t4);

    // layer 4 final gather + elu + sigmoid
    k_gather1_final<<<gW, TB>>>(t4, rowptr, edges, sc, b4, out);
}

// round 15
// speedup vs baseline: 1.9392x; 1.0345x over previous
#include <cuda_runtime.h>
#include <math.h>

#define NN 100000
#define NE 3200000
#define EPS 1e-5f

// ---------------- scratch (static device globals; no allocation) -------------
__device__ int   g_cnt[NN];               // zero-init at load; scan_apply resets each run
__device__ int   g_part[128];             // per-block partial sums for the scan
__device__ int   g_rowptr[NN + 1];
__device__ int   g_cursor[NN];
__device__ float g_dis[NN];
__device__ __align__(16)  int2  g_edge[NE + 8];   // {src, dis[src]}, +8 zero padding
__device__ __align__(256) float g_T[(size_t)NN * 128];
__device__ __align__(256) float g_A[(size_t)NN * 128];
__device__ float g_t4[NN];

// ---------------- fused gemm1 (x@W1, 128->32, R=2) + degree count -------------
// Dynamic smem: [Ws: 128*32 f32][xs: 64*(128+1) f32]
__global__ void __launch_bounds__(256) k_gemm1_count(
        const float* __restrict__ in, const float* __restrict__ W,
        float* __restrict__ t,
        const int* __restrict__ dst, int* cnt) {
    constexpr int DIN = 128, DOUT = 32, R = 2;
    constexpr int OX  = DOUT / 4;        // 8
    constexpr int GR  = 256 / OX;        // 32
    constexpr int NPB = GR * R;          // 64
    constexpr int XP  = DIN + 1;
    extern __shared__ float dynsm[];
    float* Ws = dynsm;                                   // 128*32
    float* xs = dynsm + DIN * DOUT;                      // 64*129

    const int tid = threadIdx.x;
    for (int i = tid; i < DIN * DOUT; i += 256) Ws[i] = W[i];
    __syncthreads();

    const int base = blockIdx.x * NPB;
    for (int i = tid; i < NPB * DIN; i += 256) {
        int r = i / DIN, k = i - r * DIN;
        int node = base + r;
        xs[r * XP + k] = (node < NN) ? in[(size_t)node * DIN + k] : 0.0f;
    }
    __syncthreads();

    const int ox = tid % OX;
    const int r0 = (tid / OX) * R;

    float4 acc0 = make_float4(0.f, 0.f, 0.f, 0.f);
    float4 acc1 = make_float4(0.f, 0.f, 0.f, 0.f);
#pragma unroll 4
    for (int k = 0; k < DIN; ++k) {
        float4 w = *reinterpret_cast<const float4*>(&Ws[k * DOUT + ox * 4]);
        float x0 = xs[r0 * XP + k];
        float x1 = xs[(r0 + 1) * XP + k];
        acc0.x += x0 * w.x; acc0.y += x0 * w.y; acc0.z += x0 * w.z; acc0.w += x0 * w.w;
        acc1.x += x1 * w.x; acc1.y += x1 * w.y; acc1.z += x1 * w.z; acc1.w += x1 * w.w;
    }
    if (base + r0 < NN)
        *reinterpret_cast<float4*>(&t[(size_t)(base + r0) * DOUT + ox * 4]) = acc0;
    if (base + r0 + 1 < NN)
        *reinterpret_cast<float4*>(&t[(size_t)(base + r0 + 1) * DOUT + ox * 4]) = acc1;

    const int gtid = blockIdx.x * 256 + tid;
    const int nth  = gridDim.x * 256;
    for (int i = gtid; i < NE / 4; i += nth) {
        int4 d4 = reinterpret_cast<const int4*>(dst)[i];
        atomicAdd(&cnt[d4.x], 1);
        atomicAdd(&cnt[d4.y], 1);
        atomicAdd(&cnt[d4.z], 1);
        atomicAdd(&cnt[d4.w], 1);
    }
}

// ---------------- multi-block scan (2 kernels) --------------------------------
__global__ void __launch_bounds__(1024) k_scan_part(const int* __restrict__ cnt,
                                                    int* partials) {
    __shared__ int sh[1024];
    int i = blockIdx.x * 1024 + threadIdx.x;
    sh[threadIdx.x] = (i < NN) ? cnt[i] : 0;
    __syncthreads();
    for (int o = 512; o > 0; o >>= 1) {
        if (threadIdx.x < o) sh[threadIdx.x] += sh[threadIdx.x + o];
        __syncthreads();
    }
    if (threadIdx.x == 0) partials[blockIdx.x] = sh[0];
}

__global__ void __launch_bounds__(1024) k_scan_apply(int* cnt,
        const int* __restrict__ partials,
        int* rowptr, int* cursor, float* dis) {
    constexpr int NBLK = (NN + 1023) / 1024;   // 98
    __shared__ int sp[128];
    __shared__ int sh[1024];
    const int b = blockIdx.x, t = threadIdx.x;
    if (t < 128) sp[t] = (t < NBLK) ? partials[t] : 0;
    __syncthreads();
    for (int o = 1; o < 128; o <<= 1) {
        int v = 0;
        if (t < 128 && t >= o) v = sp[t - o];
        __syncthreads();
        if (t < 128 && t >= o) sp[t] += v;
        __syncthreads();
    }
    const int base = (b > 0) ? sp[b - 1] : 0;
    const int i = b * 1024 + t;
    const int c = (i < NN) ? cnt[i] : 0;
    sh[t] = c;
    __syncthreads();
    for (int o = 1; o < 1024; o <<= 1) {
        int v = 0;
        if (t >= o) v = sh[t - o];
        __syncthreads();
        if (t >= o) sh[t] += v;
        __syncthreads();
    }
    if (i < NN) {
        int pos = base + sh[t] - c;            // exclusive prefix
        rowptr[i] = pos;
        cursor[i] = pos;
        cnt[i] = 0;
        dis[i] = rsqrtf((float)(c + 1));
    }
    if (b == 0 && t == 0) rowptr[NN] = sp[NBLK - 1];
}

// ---------------- permute: edges[pos] = {src, dis[src]} -----------------------
// dis[dst] is factored out (applied once per node in the gathers).
__global__ void __launch_bounds__(256) k_permute(const int* __restrict__ src,
                                                 const int* __restrict__ dst,
                                                 const float* __restrict__ dis,
                                                 int* cursor, int2* edges) {
    int e = blockIdx.x * blockDim.x + threadIdx.x;
    if (e >= NE) return;
    int s = src[e], d = dst[e];
    int pos = atomicAdd(&cursor[d], 1);
    edges[pos] = make_int2(s, __float_as_int(dis[s]));
}

// ---------------- sub-warp CSR gather: G nodes/warp ---------------------------
// out[node] = dn*( sum_e dis_s*t[src] + dn*t[node] ),  dn = dis[node]
// (+ bias,bn,elu if ACT, folded into scale/shift)
template<int DIM, int G, bool ACT>
__global__ void __launch_bounds__(256) k_gatherG(const float* __restrict__ t,
                         const int* __restrict__ rowptr,
                         const int2* __restrict__ edges,
                         const float* __restrict__ dis,
                         const float* __restrict__ b,
                         const float* __restrict__ bg, const float* __restrict__ bbe,
                         const float* __restrict__ bm, const float* __restrict__ bv,
                         float* __restrict__ outp) {
    constexpr int L = 32 / G;          // lanes per node
    static_assert(DIM == L * 4, "each lane owns a float4");
    const int wid  = (blockIdx.x * blockDim.x + threadIdx.x) >> 5;
    const int lane = threadIdx.x & 31;
    const int sub  = lane / L;
    const int sl   = lane % L;
    const int node = wid * G + sub;
    if (node >= NN) return;
    const int beg = rowptr[node], end = rowptr[node + 1];
    const float dn = dis[node];
    const int col = sl * 4;

    float4 p_scale, p_shift;
    if (ACT) {
        float ss0 = bg[col+0] * rsqrtf(bv[col+0] + EPS);
        float ss1 = bg[col+1] * rsqrtf(bv[col+1] + EPS);
        float ss2 = bg[col+2] * rsqrtf(bv[col+2] + EPS);
        float ss3 = bg[col+3] * rsqrtf(bv[col+3] + EPS);
        p_scale = make_float4(ss0, ss1, ss2, ss3);
        p_shift = make_float4(ss0 * (b[col+0] - bm[col+0]) + bbe[col+0],
                              ss1 * (b[col+1] - bm[col+1]) + bbe[col+1],
                              ss2 * (b[col+2] - bm[col+2]) + bbe[col+2],
                              ss3 * (b[col+3] - bm[col+3]) + bbe[col+3]);
    }

    float4 a0 = make_float4(0.f, 0.f, 0.f, 0.f);
    float4 a1 = make_float4(0.f, 0.f, 0.f, 0.f);

    int i = beg;
    for (; i + 4 <= end; i += 4) {
        int2 e0 = edges[i],   e1 = edges[i+1];
        int2 e2 = edges[i+2], e3 = edges[i+3];
        float4 v0 = *reinterpret_cast<const float4*>(&t[(size_t)e0.x * DIM + col]);
        float4 v1 = *reinterpret_cast<const float4*>(&t[(size_t)e1.x * DIM + col]);
        float4 v2 = *reinterpret_cast<const float4*>(&t[(size_t)e2.x * DIM + col]);
        float4 v3 = *reinterpret_cast<const float4*>(&t[(size_t)e3.x * DIM + col]);
        float c0 = __int_as_float(e0.y), c1 = __int_as_float(e1.y);
        float c2 = __int_as_float(e2.y), c3 = __int_as_float(e3.y);
        a0.x += c0*v0.x; a0.y += c0*v0.y; a0.z += c0*v0.z; a0.w += c0*v0.w;
        a1.x += c1*v1.x; a1.y += c1*v1.y; a1.z += c1*v1.z; a1.w += c1*v1.w;
        a0.x += c2*v2.x; a0.y += c2*v2.y; a0.z += c2*v2.z; a0.w += c2*v2.w;
        a1.x += c3*v3.x; a1.y += c3*v3.y; a1.z += c3*v3.z; a1.w += c3*v3.w;
    }
    if (i < end) {
        // predicated 4-wide tail; edges[] has +8 zero padding so loads are safe
        int2 e0 = edges[i],   e1 = edges[i+1];
        int2 e2 = edges[i+2], e3 = edges[i+3];
        float4 v0 = *reinterpret_cast<const float4*>(&t[(size_t)e0.x * DIM + col]);
        float4 v1 = *reinterpret_cast<const float4*>(&t[(size_t)e1.x * DIM + col]);
        float4 v2 = *reinterpret_cast<const float4*>(&t[(size_t)e2.x * DIM + col]);
        float4 v3 = *reinterpret_cast<const float4*>(&t[(size_t)e3.x * DIM + col]);
        float c0 = __int_as_float(e0.y);
        float c1 = (i + 1 < end) ? __int_as_float(e1.y) : 0.0f;
        float c2 = (i + 2 < end) ? __int_as_float(e2.y) : 0.0f;
        float c3 = (i + 3 < end) ? __int_as_float(e3.y) : 0.0f;
        a0.x += c0*v0.x; a0.y += c0*v0.y; a0.z += c0*v0.z; a0.w += c0*v0.w;
        a1.x += c1*v1.x; a1.y += c1*v1.y; a1.z += c1*v1.z; a1.w += c1*v1.w;
        a0.x += c2*v2.x; a0.y += c2*v2.y; a0.z += c2*v2.z; a0.w += c2*v2.w;
        a1.x += c3*v3.x; a1.y += c3*v3.y; a1.z += c3*v3.z; a1.w += c3*v3.w;
    }

    float4 sv = *reinterpret_cast<const float4*>(&t[(size_t)node * DIM + col]);
    float4 o = make_float4((a0.x + a1.x + dn * sv.x) * dn,
                           (a0.y + a1.y + dn * sv.y) * dn,
                           (a0.z + a1.z + dn * sv.z) * dn,
                           (a0.w + a1.w + dn * sv.w) * dn);
    if (ACT) {
        o.x = o.x * p_scale.x + p_shift.x;
        o.y = o.y * p_scale.y + p_shift.y;
        o.z = o.z * p_scale.z + p_shift.z;
        o.w = o.w * p_scale.w + p_shift.w;
        o.x = (o.x > 0.f) ? o.x : expm1f(o.x);
        o.y = (o.y > 0.f) ? o.y : expm1f(o.y);
        o.z = (o.z > 0.f) ? o.z : expm1f(o.z);
        o.w = (o.w > 0.f) ? o.w : expm1f(o.w);
    }
    *reinterpret_cast<float4*>(&outp[(size_t)node * DIM + col]) = o;
}

// ---------------- fused layer 2: aggregate H2 (dim32) -> gemm 32->64 ----------
// Gather phase fills the gemm's xs smem tile directly (no B round-trip).
// H3 = elu(bn2(AH2 @ W2 + b2)) -> outT
__global__ void __launch_bounds__(256) k_agg_gemm2(
        const float* __restrict__ A,        // H2, dim 32
        const int* __restrict__ rowptr,
        const int2* __restrict__ edges,
        const float* __restrict__ dis,
        const float* __restrict__ W,        // W2 [32,64]
        const float* __restrict__ b,
        const float* __restrict__ bg, const float* __restrict__ bbe,
        const float* __restrict__ bm, const float* __restrict__ bv,
        float* __restrict__ outT) {
    constexpr int DIN = 32, DOUT = 64, R = 4;
    constexpr int OX  = DOUT / 4;        // 16
    constexpr int NPB = (256 / OX) * R;  // 64
    constexpr int XP  = 36;              // row stride (floats), 16B-aligned
    __shared__ __align__(16) float Ws[DIN * DOUT];    // 8 KB
    __shared__ __align__(16) float xs[NPB * XP];      // 9 KB
    __shared__ float sh_scale[DOUT];
    __shared__ float sh_shift[DOUT];

    const int tid = threadIdx.x;
    for (int i = tid; i < DIN * DOUT; i += 256) Ws[i] = W[i];
    if (tid < DOUT) {
        float s = bg[tid] * rsqrtf(bv[tid] + EPS);
        sh_scale[tid] = s;
        sh_shift[tid] = s * (b[tid] - bm[tid]) + bbe[tid];
    }

    // ---- gather phase: 8 warps x G=4 subwarps = 32 nodes per pass, 2 passes --
    const int base = blockIdx.x * NPB;
    const int warp = tid >> 5;
    const int lane = tid & 31;
    const int sub  = lane >> 3;          // 0..3
    const int sl   = lane & 7;           // 0..7
    const int col  = sl * 4;

#pragma unroll
    for (int pass = 0; pass < 2; ++pass) {
        int r = pass * 32 + warp * 4 + sub;
        int node = base + r;
        float4 o = make_float4(0.f, 0.f, 0.f, 0.f);
        if (node < NN) {
            const int beg = rowptr[node], end = rowptr[node + 1];
            const float dn = dis[node];
            float4 a0 = make_float4(0.f, 0.f, 0.f, 0.f);
            float4 a1 = make_float4(0.f, 0.f, 0.f, 0.f);
            int i = beg;
            for (; i + 4 <= end; i += 4) {
                int2 e0 = edges[i],   e1 = edges[i+1];
                int2 e2 = edges[i+2], e3 = edges[i+3];
                float4 v0 = *reinterpret_cast<const float4*>(&A[(size_t)e0.x * DIN + col]);
                float4 v1 = *reinterpret_cast<const float4*>(&A[(size_t)e1.x * DIN + col]);
                float4 v2 = *reinterpret_cast<const float4*>(&A[(size_t)e2.x * DIN + col]);
                float4 v3 = *reinterpret_cast<const float4*>(&A[(size_t)e3.x * DIN + col]);
                float c0 = __int_as_float(e0.y), c1 = __int_as_float(e1.y);
                float c2 = __int_as_float(e2.y), c3 = __int_as_float(e3.y);
                a0.x += c0*v0.x; a0.y += c0*v0.y; a0.z += c0*v0.z; a0.w += c0*v0.w;
                a1.x += c1*v1.x; a1.y += c1*v1.y; a1.z += c1*v1.z; a1.w += c1*v1.w;
                a0.x += c2*v2.x; a0.y += c2*v2.y; a0.z += c2*v2.z; a0.w += c2*v2.w;
                a1.x += c3*v3.x; a1.y += c3*v3.y; a1.z += c3*v3.z; a1.w += c3*v3.w;
            }
            if (i < end) {
                int2 e0 = edges[i],   e1 = edges[i+1];
                int2 e2 = edges[i+2], e3 = edges[i+3];
                float4 v0 = *reinterpret_cast<const float4*>(&A[(size_t)e0.x * DIN + col]);
                float4 v1 = *reinterpret_cast<const float4*>(&A[(size_t)e1.x * DIN + col]);
                float4 v2 = *reinterpret_cast<const float4*>(&A[(size_t)e2.x * DIN + col]);
                float4 v3 = *reinterpret_cast<const float4*>(&A[(size_t)e3.x * DIN + col]);
                float c0 = __int_as_float(e0.y);
                float c1 = (i + 1 < end) ? __int_as_float(e1.y) : 0.0f;
                float c2 = (i + 2 < end) ? __int_as_float(e2.y) : 0.0f;
                float c3 = (i + 3 < end) ? __int_as_float(e3.y) : 0.0f;
                a0.x += c0*v0.x; a0.y += c0*v0.y; a0.z += c0*v0.z; a0.w += c0*v0.w;
                a1.x += c1*v1.x; a1.y += c1*v1.y; a1.z += c1*v1.z; a1.w += c1*v1.w;
                a0.x += c2*v2.x; a0.y += c2*v2.y; a0.z += c2*v2.z; a0.w += c2*v2.w;
                a1.x += c3*v3.x; a1.y += c3*v3.y; a1.z += c3*v3.z; a1.w += c3*v3.w;
            }
            float4 sv = *reinterpret_cast<const float4*>(&A[(size_t)node * DIN + col]);
            o = make_float4((a0.x + a1.x + dn * sv.x) * dn,
                            (a0.y + a1.y + dn * sv.y) * dn,
                            (a0.z + a1.z + dn * sv.z) * dn,
                            (a0.w + a1.w + dn * sv.w) * dn);
        }
        *reinterpret_cast<float4*>(&xs[r * XP + col]) = o;
    }
    __syncthreads();

    // ---- gemm phase: R=4 rows per thread ------------------------------------
    const int ox = tid % OX;
    const int r0 = (tid / OX) * R;

    float4 acc[R];
#pragma unroll
    for (int j = 0; j < R; ++j) acc[j] = make_float4(0.f, 0.f, 0.f, 0.f);

#pragma unroll 4
    for (int k = 0; k < DIN; ++k) {
        float4 w = *reinterpret_cast<const float4*>(&Ws[k * DOUT + ox * 4]);
#pragma unroll
        for (int j = 0; j < R; ++j) {
            float xv = xs[(r0 + j) * XP + k];
            acc[j].x += xv * w.x; acc[j].y += xv * w.y;
            acc[j].z += xv * w.z; acc[j].w += xv * w.w;
        }
    }

    const float4 s4 = *reinterpret_cast<const float4*>(&sh_scale[ox * 4]);
    const float4 h4 = *reinterpret_cast<const float4*>(&sh_shift[ox * 4]);
#pragma unroll
    for (int j = 0; j < R; ++j) {
        int node = base + r0 + j;
        if (node >= NN) continue;
        float4 o = acc[j];
        o.x = o.x * s4.x + h4.x; o.y = o.y * s4.y + h4.y;
        o.z = o.z * s4.z + h4.z; o.w = o.w * s4.w + h4.w;
        o.x = (o.x > 0.f) ? o.x : expm1f(o.x);
        o.y = (o.y > 0.f) ? o.y : expm1f(o.y);
        o.z = (o.z > 0.f) ? o.z : expm1f(o.z);
        o.w = (o.w > 0.f) ? o.w : expm1f(o.w);
        *reinterpret_cast<float4*>(&outT[(size_t)node * DOUT + ox * 4]) = o;
    }
}

// ---------------- gemm3 fused with final dot ----------------------------------
__global__ void __launch_bounds__(256) k_gemm3_dot(
        const float* __restrict__ in,
        const float* __restrict__ W,
        const float* __restrict__ b,
        const float* __restrict__ bg, const float* __restrict__ bbe,
        const float* __restrict__ bm, const float* __restrict__ bv,
        const float* __restrict__ W4,
        float* __restrict__ t4) {
    constexpr int DIN = 64, DOUT = 128, R = 4;
    constexpr int OX  = DOUT / 4;        // 32
    constexpr int GR  = 256 / OX;        // 8
    constexpr int NPB = GR * R;          // 32
    __shared__ __align__(16) float Ws[DIN * DOUT];
    __shared__ float xs[NPB][DIN + 1];
    __shared__ float sh_scale[DOUT];
    __shared__ float sh_shift[DOUT];
    __shared__ __align__(16) float w4s[DOUT];

    const int tid = threadIdx.x;
    for (int i = tid; i < DIN * DOUT; i += 256) Ws[i] = W[i];
    if (tid < DOUT) {
        float s = bg[tid] * rsqrtf(bv[tid] + EPS);
        sh_scale[tid] = s;
        sh_shift[tid] = s * (b[tid] - bm[tid]) + bbe[tid];
        w4s[tid] = W4[tid];
    }
    __syncthreads();

    const int base = blockIdx.x * NPB;
    for (int i = tid; i < NPB * DIN; i += 256) {
        int r = i / DIN, k = i - r * DIN;
        int node = base + r;
        xs[r][k] = (node < NN) ? in[(size_t)node * DIN + k] : 0.0f;
    }
    __syncthreads();

    const int ox = tid % OX;             // == lane
    const int r0 = (tid / OX) * R;

    float4 acc[R];
#pragma unroll
    for (int j = 0; j < R; ++j) acc[j] = make_float4(0.f, 0.f, 0.f, 0.f);

#pragma unroll 4
    for (int k = 0; k < DIN; ++k) {
        float4 w = *reinterpret_cast<const float4*>(&Ws[k * DOUT + ox * 4]);
#pragma unroll
        for (int j = 0; j < R; ++j) {
            float xv = xs[r0 + j][k];
            acc[j].x += xv * w.x; acc[j].y += xv * w.y;
            acc[j].z += xv * w.z; acc[j].w += xv * w.w;
        }
    }

    const float4 s4 = *reinterpret_cast<const float4*>(&sh_scale[ox * 4]);
    const float4 h4 = *reinterpret_cast<const float4*>(&sh_shift[ox * 4]);
    const float4 w4 = *reinterpret_cast<const float4*>(&w4s[ox * 4]);
#pragma unroll
    for (int j = 0; j < R; ++j) {
        float4 o = acc[j];
        o.x = o.x * s4.x + h4.x; o.y = o.y * s4.y + h4.y;
        o.z = o.z * s4.z + h4.z; o.w = o.w * s4.w + h4.w;
        o.x = (o.x > 0.f) ? o.x : expm1f(o.x);
        o.y = (o.y > 0.f) ? o.y : expm1f(o.y);
        o.z = (o.z > 0.f) ? o.z : expm1f(o.z);
        o.w = (o.w > 0.f) ? o.w : expm1f(o.w);
        float p = o.x * w4.x + o.y * w4.y + o.z * w4.z + o.w * w4.w;
#pragma unroll
        for (int sh = 16; sh > 0; sh >>= 1)
            p += __shfl_xor_sync(0xffffffffu, p, sh);
        int node = base + r0 + j;
        if (ox == 0 && node < NN) t4[node] = p;
    }
}

__global__ void __launch_bounds__(256) k_gather1_final(const float* __restrict__ t4,
                                const int* __restrict__ rowptr,
                                const int2* __restrict__ edges,
                                const float* __restrict__ dis,
                                const float* __restrict__ b4,
                                float* __restrict__ out) {
    const int warp = (blockIdx.x * blockDim.x + threadIdx.x) >> 5;
    const int lane = threadIdx.x & 31;
    if (warp >= NN) return;
    const int node = warp;
    const int beg = rowptr[node], end = rowptr[node + 1];
    float acc = 0.0f;
    for (int i = beg + lane; i < end; i += 32) {
        int2 e = edges[i];
        acc += __int_as_float(e.y) * t4[e.x];
    }
#pragma unroll
    for (int o = 16; o > 0; o >>= 1) acc += __shfl_xor_sync(0xffffffffu, acc, o);
    if (lane == 0) {
        float dn = dis[node];
        float x = (acc + dn * t4[node]) * dn + b4[0];
        x = (x > 0.0f) ? x : expm1f(x);
        out[node] = 1.0f / (1.0f + expf(-x));
    }
}

// ---------------- launch -----------------------------------------------------
extern "C" void kernel_launch(void* const* d_in, const int* in_sizes, int n_in,
                              void* d_out, int out_size) {
    const float* x   = (const float*)d_in[0];
    const int*   src = (const int*)  d_in[1];
    const int*   dst = (const int*)  d_in[2];
    const float* W1 = (const float*)d_in[3];  const float* b1 = (const float*)d_in[4];
    const float* W2 = (const float*)d_in[5];  const float* b2 = (const float*)d_in[6];
    const float* W3 = (const float*)d_in[7];  const float* b3 = (const float*)d_in[8];
    const float* W4 = (const float*)d_in[9];  const float* b4 = (const float*)d_in[10];
    const float* g1 = (const float*)d_in[11]; const float* be1 = (const float*)d_in[12];
    const float* m1 = (const float*)d_in[13]; const float* v1  = (const float*)d_in[14];
    const float* g2 = (const float*)d_in[15]; const float* be2 = (const float*)d_in[16];
    const float* m2 = (const float*)d_in[17]; const float* v2  = (const float*)d_in[18];
    const float* g3 = (const float*)d_in[19]; const float* be3 = (const float*)d_in[20];
    const float* m3 = (const float*)d_in[21]; const float* v3  = (const float*)d_in[22];
    float* out = (float*)d_out;

    void *pcnt, *ppart, *prp, *pcur, *pdis, *pedge, *pT, *pA, *pt4;
    cudaGetSymbolAddress(&pcnt, g_cnt);
    cudaGetSymbolAddress(&ppart, g_part);
    cudaGetSymbolAddress(&prp,  g_rowptr);
    cudaGetSymbolAddress(&pcur, g_cursor);
    cudaGetSymbolAddress(&pdis, g_dis);
    cudaGetSymbolAddress(&pedge, g_edge);
    cudaGetSymbolAddress(&pT, g_T);
    cudaGetSymbolAddress(&pA, g_A);
    cudaGetSymbolAddress(&pt4, g_t4);
    int* cnt = (int*)pcnt; int* part = (int*)ppart;
    int* rowptr = (int*)prp; int* cursor = (int*)pcur;
    float* dis = (float*)pdis;
    int2* edges = (int2*)pedge;
    float* T = (float*)pT; float* A = (float*)pA;
    float* t4 = (float*)pt4;

    const int TB = 256;
    const int gE = (NE + TB - 1) / TB;
    const int gW = (NN + 7) / 8;                 // warp-per-node kernels
    const int gW4 = (NN + 4 * 8 - 1) / (4 * 8);  // G=4 sub-warp gather (dim 32)
    const int gW2 = (NN + 2 * 8 - 1) / (2 * 8);  // G=2 sub-warp gather (dim 64)
    const int NBLK = (NN + 1023) / 1024;         // 98 scan blocks

    const int SM1 = 128*32*4 + 64*129*4;   // 49408 bytes dynamic smem for gemm1
    cudaFuncSetAttribute((const void*)k_gemm1_count,
                         cudaFuncAttributeMaxDynamicSharedMemorySize, SM1);

    // (1) gemm1 (x@W1 -> T) fused with degree count
    k_gemm1_count<<<(NN + 63) / 64, TB, SM1>>>(x, W1, T, dst, cnt);
    // (2,3) multi-block scan
    k_scan_part<<<NBLK, 1024>>>(cnt, part);
    k_scan_apply<<<NBLK, 1024>>>(cnt, part, rowptr, cursor, dis);
    // (4) permute  [profiled slot — A/B for the dis-factoring change]
    k_permute<<<gE, TB>>>(src, dst, dis, cursor, edges);

    // layer 1 gather dim32 (G=4) + bias+bn1+elu -> H2 (A)
    k_gatherG<32, 4, true><<<gW4, TB>>>(T, rowptr, edges, dis, b1, g1, be1, m1, v1, A);

    // layer 2 fused: aggregate H2 (dim32) into smem, gemm 32->64 + bn2+elu -> T
    k_agg_gemm2<<<(NN + 63) / 64, TB>>>(A, rowptr, edges, dis,
                                        W2, b2, g2, be2, m2, v2, T);

    // layer 3: aggregate H3 (dim64, G=2) -> A; gemm3 fused with W4 dot -> t4
    k_gatherG<64, 2, false><<<gW2, TB>>>(T, rowptr, edges, dis,
                                    nullptr, nullptr, nullptr, nullptr, nullptr, A);
    k_gemm3_dot<<<(NN + 31) / 32, TB>>>(A, W3, b3, g3, be3, m3, v3, W4, t4);

    // layer 4 final gather + elu + sigmoid
    k_gather1_final<<<gW, TB>>>(t4, rowptr, edges, dis, b4, out);
}

// round 16
// speedup vs baseline: 1.9892x; 1.0258x over previous
#include <cuda_runtime.h>
#include <math.h>

#define NN 100000
#define NE 3200000
#define EPS 1e-5f

// ---------------- scratch (static device globals; no allocation) -------------
__device__ int   g_cnt[NN];               // zero-init at load; scan_apply resets each run
__device__ int   g_part[128];             // per-block partial sums for the scan
__device__ int   g_rowptr[NN + 1];
__device__ int   g_cursor[NN];
__device__ float g_dis[NN];
__device__ __align__(16)  int2  g_edge[NE + 8];   // {src, dis[src]}, +8 zero padding
__device__ __align__(256) float g_T[(size_t)NN * 128];
__device__ __align__(256) float g_A[(size_t)NN * 128];
__device__ float g_t4[NN];

// ---------------- fused gemm1 (x@W1, 128->32, R=2) + degree count -------------
// Dynamic smem: [Ws: 128*32 f32][xs: 64*(128+1) f32]
__global__ void __launch_bounds__(256) k_gemm1_count(
        const float* __restrict__ in, const float* __restrict__ W,
        float* __restrict__ t,
        const int* __restrict__ dst, int* cnt) {
    constexpr int DIN = 128, DOUT = 32, R = 2;
    constexpr int OX  = DOUT / 4;        // 8
    constexpr int GR  = 256 / OX;        // 32
    constexpr int NPB = GR * R;          // 64
    constexpr int XP  = DIN + 1;
    extern __shared__ float dynsm[];
    float* Ws = dynsm;                                   // 128*32
    float* xs = dynsm + DIN * DOUT;                      // 64*129

    const int tid = threadIdx.x;
    for (int i = tid; i < DIN * DOUT; i += 256) Ws[i] = W[i];
    __syncthreads();

    const int base = blockIdx.x * NPB;
    for (int i = tid; i < NPB * DIN; i += 256) {
        int r = i / DIN, k = i - r * DIN;
        int node = base + r;
        xs[r * XP + k] = (node < NN) ? in[(size_t)node * DIN + k] : 0.0f;
    }
    __syncthreads();

    const int ox = tid % OX;
    const int r0 = (tid / OX) * R;

    float4 acc0 = make_float4(0.f, 0.f, 0.f, 0.f);
    float4 acc1 = make_float4(0.f, 0.f, 0.f, 0.f);
#pragma unroll 4
    for (int k = 0; k < DIN; ++k) {
        float4 w = *reinterpret_cast<const float4*>(&Ws[k * DOUT + ox * 4]);
        float x0 = xs[r0 * XP + k];
        float x1 = xs[(r0 + 1) * XP + k];
        acc0.x += x0 * w.x; acc0.y += x0 * w.y; acc0.z += x0 * w.z; acc0.w += x0 * w.w;
        acc1.x += x1 * w.x; acc1.y += x1 * w.y; acc1.z += x1 * w.z; acc1.w += x1 * w.w;
    }
    if (base + r0 < NN)
        *reinterpret_cast<float4*>(&t[(size_t)(base + r0) * DOUT + ox * 4]) = acc0;
    if (base + r0 + 1 < NN)
        *reinterpret_cast<float4*>(&t[(size_t)(base + r0 + 1) * DOUT + ox * 4]) = acc1;

    const int gtid = blockIdx.x * 256 + tid;
    const int nth  = gridDim.x * 256;
    for (int i = gtid; i < NE / 4; i += nth) {
        int4 d4 = reinterpret_cast<const int4*>(dst)[i];
        atomicAdd(&cnt[d4.x], 1);
        atomicAdd(&cnt[d4.y], 1);
        atomicAdd(&cnt[d4.z], 1);
        atomicAdd(&cnt[d4.w], 1);
    }
}

// ---------------- multi-block scan (2 kernels) --------------------------------
__global__ void __launch_bounds__(1024) k_scan_part(const int* __restrict__ cnt,
                                                    int* partials) {
    __shared__ int sh[1024];
    int i = blockIdx.x * 1024 + threadIdx.x;
    sh[threadIdx.x] = (i < NN) ? cnt[i] : 0;
    __syncthreads();
    for (int o = 512; o > 0; o >>= 1) {
        if (threadIdx.x < o) sh[threadIdx.x] += sh[threadIdx.x + o];
        __syncthreads();
    }
    if (threadIdx.x == 0) partials[blockIdx.x] = sh[0];
}

__global__ void __launch_bounds__(1024) k_scan_apply(int* cnt,
        const int* __restrict__ partials,
        int* rowptr, int* cursor, float* dis) {
    constexpr int NBLK = (NN + 1023) / 1024;   // 98
    __shared__ int sp[128];
    __shared__ int sh[1024];
    const int b = blockIdx.x, t = threadIdx.x;
    if (t < 128) sp[t] = (t < NBLK) ? partials[t] : 0;
    __syncthreads();
    for (int o = 1; o < 128; o <<= 1) {
        int v = 0;
        if (t < 128 && t >= o) v = sp[t - o];
        __syncthreads();
        if (t < 128 && t >= o) sp[t] += v;
        __syncthreads();
    }
    const int base = (b > 0) ? sp[b - 1] : 0;
    const int i = b * 1024 + t;
    const int c = (i < NN) ? cnt[i] : 0;
    sh[t] = c;
    __syncthreads();
    for (int o = 1; o < 1024; o <<= 1) {
        int v = 0;
        if (t >= o) v = sh[t - o];
        __syncthreads();
        if (t >= o) sh[t] += v;
        __syncthreads();
    }
    if (i < NN) {
        int pos = base + sh[t] - c;            // exclusive prefix
        rowptr[i] = pos;
        cursor[i] = pos;
        cnt[i] = 0;
        dis[i] = rsqrtf((float)(c + 1));
    }
    if (b == 0 && t == 0) rowptr[NN] = sp[NBLK - 1];
}

// ---------------- permute: edges[pos] = {src, dis[src]} -----------------------
__global__ void __launch_bounds__(256) k_permute(const int* __restrict__ src,
                                                 const int* __restrict__ dst,
                                                 const float* __restrict__ dis,
                                                 int* cursor, int2* edges) {
    int e = blockIdx.x * blockDim.x + threadIdx.x;
    if (e >= NE) return;
    int s = src[e], d = dst[e];
    int pos = atomicAdd(&cursor[d], 1);
    edges[pos] = make_int2(s, __float_as_int(dis[s]));
}

// ---------------- sub-warp CSR gather: G nodes/warp ---------------------------
// out[node] = dn*( sum_e dis_s*t[src] + dn*t[node] ),  dn = dis[node]
template<int DIM, int G, bool ACT>
__global__ void __launch_bounds__(256) k_gatherG(const float* __restrict__ t,
                         const int* __restrict__ rowptr,
                         const int2* __restrict__ edges,
                         const float* __restrict__ dis,
                         const float* __restrict__ b,
                         const float* __restrict__ bg, const float* __restrict__ bbe,
                         const float* __restrict__ bm, const float* __restrict__ bv,
                         float* __restrict__ outp) {
    constexpr int L = 32 / G;          // lanes per node
    static_assert(DIM == L * 4, "each lane owns a float4");
    const int wid  = (blockIdx.x * blockDim.x + threadIdx.x) >> 5;
    const int lane = threadIdx.x & 31;
    const int sub  = lane / L;
    const int sl   = lane % L;
    const int node = wid * G + sub;
    if (node >= NN) return;
    const int beg = rowptr[node], end = rowptr[node + 1];
    const float dn = dis[node];
    const int col = sl * 4;

    float4 p_scale, p_shift;
    if (ACT) {
        float ss0 = bg[col+0] * rsqrtf(bv[col+0] + EPS);
        float ss1 = bg[col+1] * rsqrtf(bv[col+1] + EPS);
        float ss2 = bg[col+2] * rsqrtf(bv[col+2] + EPS);
        float ss3 = bg[col+3] * rsqrtf(bv[col+3] + EPS);
        p_scale = make_float4(ss0, ss1, ss2, ss3);
        p_shift = make_float4(ss0 * (b[col+0] - bm[col+0]) + bbe[col+0],
                              ss1 * (b[col+1] - bm[col+1]) + bbe[col+1],
                              ss2 * (b[col+2] - bm[col+2]) + bbe[col+2],
                              ss3 * (b[col+3] - bm[col+3]) + bbe[col+3]);
    }

    float4 a0 = make_float4(0.f, 0.f, 0.f, 0.f);
    float4 a1 = make_float4(0.f, 0.f, 0.f, 0.f);

    int i = beg;
    for (; i + 4 <= end; i += 4) {
        int2 e0 = edges[i],   e1 = edges[i+1];
        int2 e2 = edges[i+2], e3 = edges[i+3];
        float4 v0 = *reinterpret_cast<const float4*>(&t[(size_t)e0.x * DIM + col]);
        float4 v1 = *reinterpret_cast<const float4*>(&t[(size_t)e1.x * DIM + col]);
        float4 v2 = *reinterpret_cast<const float4*>(&t[(size_t)e2.x * DIM + col]);
        float4 v3 = *reinterpret_cast<const float4*>(&t[(size_t)e3.x * DIM + col]);
        float c0 = __int_as_float(e0.y), c1 = __int_as_float(e1.y);
        float c2 = __int_as_float(e2.y), c3 = __int_as_float(e3.y);
        a0.x += c0*v0.x; a0.y += c0*v0.y; a0.z += c0*v0.z; a0.w += c0*v0.w;
        a1.x += c1*v1.x; a1.y += c1*v1.y; a1.z += c1*v1.z; a1.w += c1*v1.w;
        a0.x += c2*v2.x; a0.y += c2*v2.y; a0.z += c2*v2.z; a0.w += c2*v2.w;
        a1.x += c3*v3.x; a1.y += c3*v3.y; a1.z += c3*v3.z; a1.w += c3*v3.w;
    }
    if (i < end) {
        int2 e0 = edges[i],   e1 = edges[i+1];
        int2 e2 = edges[i+2], e3 = edges[i+3];
        float4 v0 = *reinterpret_cast<const float4*>(&t[(size_t)e0.x * DIM + col]);
        float4 v1 = *reinterpret_cast<const float4*>(&t[(size_t)e1.x * DIM + col]);
        float4 v2 = *reinterpret_cast<const float4*>(&t[(size_t)e2.x * DIM + col]);
        float4 v3 = *reinterpret_cast<const float4*>(&t[(size_t)e3.x * DIM + col]);
        float c0 = __int_as_float(e0.y);
        float c1 = (i + 1 < end) ? __int_as_float(e1.y) : 0.0f;
        float c2 = (i + 2 < end) ? __int_as_float(e2.y) : 0.0f;
        float c3 = (i + 3 < end) ? __int_as_float(e3.y) : 0.0f;
        a0.x += c0*v0.x; a0.y += c0*v0.y; a0.z += c0*v0.z; a0.w += c0*v0.w;
        a1.x += c1*v1.x; a1.y += c1*v1.y; a1.z += c1*v1.z; a1.w += c1*v1.w;
        a0.x += c2*v2.x; a0.y += c2*v2.y; a0.z += c2*v2.z; a0.w += c2*v2.w;
        a1.x += c3*v3.x; a1.y += c3*v3.y; a1.z += c3*v3.z; a1.w += c3*v3.w;
    }

    float4 sv = *reinterpret_cast<const float4*>(&t[(size_t)node * DIM + col]);
    float4 o = make_float4((a0.x + a1.x + dn * sv.x) * dn,
                           (a0.y + a1.y + dn * sv.y) * dn,
                           (a0.z + a1.z + dn * sv.z) * dn,
                           (a0.w + a1.w + dn * sv.w) * dn);
    if (ACT) {
        o.x = o.x * p_scale.x + p_shift.x;
        o.y = o.y * p_scale.y + p_shift.y;
        o.z = o.z * p_scale.z + p_shift.z;
        o.w = o.w * p_scale.w + p_shift.w;
        o.x = (o.x > 0.f) ? o.x : expm1f(o.x);
        o.y = (o.y > 0.f) ? o.y : expm1f(o.y);
        o.z = (o.z > 0.f) ? o.z : expm1f(o.z);
        o.w = (o.w > 0.f) ? o.w : expm1f(o.w);
    }
    *reinterpret_cast<float4*>(&outp[(size_t)node * DIM + col]) = o;
}

// ---------------- fused layer 2: aggregate H2 (dim32) -> gemm 32->64 ----------
__global__ void __launch_bounds__(256) k_agg_gemm2(
        const float* __restrict__ A,        // H2, dim 32
        const int* __restrict__ rowptr,
        const int2* __restrict__ edges,
        const float* __restrict__ dis,
        const float* __restrict__ W,        // W2 [32,64]
        const float* __restrict__ b,
        const float* __restrict__ bg, const float* __restrict__ bbe,
        const float* __restrict__ bm, const float* __restrict__ bv,
        float* __restrict__ outT) {
    constexpr int DIN = 32, DOUT = 64, R = 4;
    constexpr int OX  = DOUT / 4;        // 16
    constexpr int NPB = (256 / OX) * R;  // 64
    constexpr int XP  = 36;              // row stride (floats), 16B-aligned
    __shared__ __align__(16) float Ws[DIN * DOUT];    // 8 KB
    __shared__ __align__(16) float xs[NPB * XP];      // 9 KB
    __shared__ float sh_scale[DOUT];
    __shared__ float sh_shift[DOUT];

    const int tid = threadIdx.x;
    for (int i = tid; i < DIN * DOUT; i += 256) Ws[i] = W[i];
    if (tid < DOUT) {
        float s = bg[tid] * rsqrtf(bv[tid] + EPS);
        sh_scale[tid] = s;
        sh_shift[tid] = s * (b[tid] - bm[tid]) + bbe[tid];
    }

    // ---- gather phase: 8 warps x G=4 subwarps = 32 nodes per pass, 2 passes --
    const int base = blockIdx.x * NPB;
    const int warp = tid >> 5;
    const int lane = tid & 31;
    const int sub  = lane >> 3;          // 0..3
    const int sl   = lane & 7;           // 0..7
    const int col  = sl * 4;

#pragma unroll
    for (int pass = 0; pass < 2; ++pass) {
        int r = pass * 32 + warp * 4 + sub;
        int node = base + r;
        float4 o = make_float4(0.f, 0.f, 0.f, 0.f);
        if (node < NN) {
            const int beg = rowptr[node], end = rowptr[node + 1];
            const float dn = dis[node];
            float4 a0 = make_float4(0.f, 0.f, 0.f, 0.f);
            float4 a1 = make_float4(0.f, 0.f, 0.f, 0.f);
            int i = beg;
            for (; i + 4 <= end; i += 4) {
                int2 e0 = edges[i],   e1 = edges[i+1];
                int2 e2 = edges[i+2], e3 = edges[i+3];
                float4 v0 = *reinterpret_cast<const float4*>(&A[(size_t)e0.x * DIN + col]);
                float4 v1 = *reinterpret_cast<const float4*>(&A[(size_t)e1.x * DIN + col]);
                float4 v2 = *reinterpret_cast<const float4*>(&A[(size_t)e2.x * DIN + col]);
                float4 v3 = *reinterpret_cast<const float4*>(&A[(size_t)e3.x * DIN + col]);
                float c0 = __int_as_float(e0.y), c1 = __int_as_float(e1.y);
                float c2 = __int_as_float(e2.y), c3 = __int_as_float(e3.y);
                a0.x += c0*v0.x; a0.y += c0*v0.y; a0.z += c0*v0.z; a0.w += c0*v0.w;
                a1.x += c1*v1.x; a1.y += c1*v1.y; a1.z += c1*v1.z; a1.w += c1*v1.w;
                a0.x += c2*v2.x; a0.y += c2*v2.y; a0.z += c2*v2.z; a0.w += c2*v2.w;
                a1.x += c3*v3.x; a1.y += c3*v3.y; a1.z += c3*v3.z; a1.w += c3*v3.w;
            }
            if (i < end) {
                int2 e0 = edges[i],   e1 = edges[i+1];
                int2 e2 = edges[i+2], e3 = edges[i+3];
                float4 v0 = *reinterpret_cast<const float4*>(&A[(size_t)e0.x * DIN + col]);
                float4 v1 = *reinterpret_cast<const float4*>(&A[(size_t)e1.x * DIN + col]);
                float4 v2 = *reinterpret_cast<const float4*>(&A[(size_t)e2.x * DIN + col]);
                float4 v3 = *reinterpret_cast<const float4*>(&A[(size_t)e3.x * DIN + col]);
                float c0 = __int_as_float(e0.y);
                float c1 = (i + 1 < end) ? __int_as_float(e1.y) : 0.0f;
                float c2 = (i + 2 < end) ? __int_as_float(e2.y) : 0.0f;
                float c3 = (i + 3 < end) ? __int_as_float(e3.y) : 0.0f;
                a0.x += c0*v0.x; a0.y += c0*v0.y; a0.z += c0*v0.z; a0.w += c0*v0.w;
                a1.x += c1*v1.x; a1.y += c1*v1.y; a1.z += c1*v1.z; a1.w += c1*v1.w;
                a0.x += c2*v2.x; a0.y += c2*v2.y; a0.z += c2*v2.z; a0.w += c2*v2.w;
                a1.x += c3*v3.x; a1.y += c3*v3.y; a1.z += c3*v3.z; a1.w += c3*v3.w;
            }
            float4 sv = *reinterpret_cast<const float4*>(&A[(size_t)node * DIN + col]);
            o = make_float4((a0.x + a1.x + dn * sv.x) * dn,
                            (a0.y + a1.y + dn * sv.y) * dn,
                            (a0.z + a1.z + dn * sv.z) * dn,
                            (a0.w + a1.w + dn * sv.w) * dn);
        }
        *reinterpret_cast<float4*>(&xs[r * XP + col]) = o;
    }
    __syncthreads();

    // ---- gemm phase: R=4 rows per thread ------------------------------------
    const int ox = tid % OX;
    const int r0 = (tid / OX) * R;

    float4 acc[R];
#pragma unroll
    for (int j = 0; j < R; ++j) acc[j] = make_float4(0.f, 0.f, 0.f, 0.f);

#pragma unroll 4
    for (int k = 0; k < DIN; ++k) {
        float4 w = *reinterpret_cast<const float4*>(&Ws[k * DOUT + ox * 4]);
#pragma unroll
        for (int j = 0; j < R; ++j) {
            float xv = xs[(r0 + j) * XP + k];
            acc[j].x += xv * w.x; acc[j].y += xv * w.y;
            acc[j].z += xv * w.z; acc[j].w += xv * w.w;
        }
    }

    const float4 s4 = *reinterpret_cast<const float4*>(&sh_scale[ox * 4]);
    const float4 h4 = *reinterpret_cast<const float4*>(&sh_shift[ox * 4]);
#pragma unroll
    for (int j = 0; j < R; ++j) {
        int node = base + r0 + j;
        if (node >= NN) continue;
        float4 o = acc[j];
        o.x = o.x * s4.x + h4.x; o.y = o.y * s4.y + h4.y;
        o.z = o.z * s4.z + h4.z; o.w = o.w * s4.w + h4.w;
        o.x = (o.x > 0.f) ? o.x : expm1f(o.x);
        o.y = (o.y > 0.f) ? o.y : expm1f(o.y);
        o.z = (o.z > 0.f) ? o.z : expm1f(o.z);
        o.w = (o.w > 0.f) ? o.w : expm1f(o.w);
        *reinterpret_cast<float4*>(&outT[(size_t)node * DOUT + ox * 4]) = o;
    }
}

// ---------------- fused layer 3+4a: aggregate H3 (dim64) -> gemm3 -> W4 dot ---
// xs tile filled by subwarp gather (G=2), then t4 = elu(bn3(AH3@W3+b3)) @ W4.
// H4 and AH3 never touch GMEM.
__global__ void __launch_bounds__(256) k_agg_gemm3_dot(
        const float* __restrict__ T,        // H3, dim 64
        const int* __restrict__ rowptr,
        const int2* __restrict__ edges,
        const float* __restrict__ dis,
        const float* __restrict__ W,        // W3 [64,128]
        const float* __restrict__ b,
        const float* __restrict__ bg, const float* __restrict__ bbe,
        const float* __restrict__ bm, const float* __restrict__ bv,
        const float* __restrict__ W4,
        float* __restrict__ t4) {
    constexpr int DIN = 64, DOUT = 128, R = 4;
    constexpr int OX  = DOUT / 4;        // 32
    constexpr int NPB = (256 / OX) * R;  // 32
    constexpr int XP  = 68;              // row stride (floats), 16B-aligned
    __shared__ __align__(16) float Ws[DIN * DOUT];    // 32 KB
    __shared__ __align__(16) float xs[NPB * XP];      // 8.7 KB
    __shared__ float sh_scale[DOUT];
    __shared__ float sh_shift[DOUT];
    __shared__ __align__(16) float w4s[DOUT];

    const int tid = threadIdx.x;
    for (int i = tid; i < DIN * DOUT; i += 256) Ws[i] = W[i];
    if (tid < DOUT) {
        float s = bg[tid] * rsqrtf(bv[tid] + EPS);
        sh_scale[tid] = s;
        sh_shift[tid] = s * (b[tid] - bm[tid]) + bbe[tid];
        w4s[tid] = W4[tid];
    }

    // ---- gather phase: 8 warps x G=2 subwarps = 16 nodes per pass, 2 passes --
    const int base = blockIdx.x * NPB;
    const int warp = tid >> 5;
    const int lane = tid & 31;
    const int sub  = lane >> 4;          // 0..1
    const int sl   = lane & 15;          // 0..15
    const int col  = sl * 4;

#pragma unroll
    for (int pass = 0; pass < 2; ++pass) {
        int r = pass * 16 + warp * 2 + sub;
        int node = base + r;
        float4 o = make_float4(0.f, 0.f, 0.f, 0.f);
        if (node < NN) {
            const int beg = rowptr[node], end = rowptr[node + 1];
            const float dn = dis[node];
            float4 a0 = make_float4(0.f, 0.f, 0.f, 0.f);
            float4 a1 = make_float4(0.f, 0.f, 0.f, 0.f);
            int i = beg;
            for (; i + 4 <= end; i += 4) {
                int2 e0 = edges[i],   e1 = edges[i+1];
                int2 e2 = edges[i+2], e3 = edges[i+3];
                float4 v0 = *reinterpret_cast<const float4*>(&T[(size_t)e0.x * DIN + col]);
                float4 v1 = *reinterpret_cast<const float4*>(&T[(size_t)e1.x * DIN + col]);
                float4 v2 = *reinterpret_cast<const float4*>(&T[(size_t)e2.x * DIN + col]);
                float4 v3 = *reinterpret_cast<const float4*>(&T[(size_t)e3.x * DIN + col]);
                float c0 = __int_as_float(e0.y), c1 = __int_as_float(e1.y);
                float c2 = __int_as_float(e2.y), c3 = __int_as_float(e3.y);
                a0.x += c0*v0.x; a0.y += c0*v0.y; a0.z += c0*v0.z; a0.w += c0*v0.w;
                a1.x += c1*v1.x; a1.y += c1*v1.y; a1.z += c1*v1.z; a1.w += c1*v1.w;
                a0.x += c2*v2.x; a0.y += c2*v2.y; a0.z += c2*v2.z; a0.w += c2*v2.w;
                a1.x += c3*v3.x; a1.y += c3*v3.y; a1.z += c3*v3.z; a1.w += c3*v3.w;
            }
            if (i < end) {
                int2 e0 = edges[i],   e1 = edges[i+1];
                int2 e2 = edges[i+2], e3 = edges[i+3];
                float4 v0 = *reinterpret_cast<const float4*>(&T[(size_t)e0.x * DIN + col]);
                float4 v1 = *reinterpret_cast<const float4*>(&T[(size_t)e1.x * DIN + col]);
                float4 v2 = *reinterpret_cast<const float4*>(&T[(size_t)e2.x * DIN + col]);
                float4 v3 = *reinterpret_cast<const float4*>(&T[(size_t)e3.x * DIN + col]);
                float c0 = __int_as_float(e0.y);
                float c1 = (i + 1 < end) ? __int_as_float(e1.y) : 0.0f;
                float c2 = (i + 2 < end) ? __int_as_float(e2.y) : 0.0f;
                float c3 = (i + 3 < end) ? __int_as_float(e3.y) : 0.0f;
                a0.x += c0*v0.x; a0.y += c0*v0.y; a0.z += c0*v0.z; a0.w += c0*v0.w;
                a1.x += c1*v1.x; a1.y += c1*v1.y; a1.z += c1*v1.z; a1.w += c1*v1.w;
                a0.x += c2*v2.x; a0.y += c2*v2.y; a0.z += c2*v2.z; a0.w += c2*v2.w;
                a1.x += c3*v3.x; a1.y += c3*v3.y; a1.z += c3*v3.z; a1.w += c3*v3.w;
            }
            float4 sv = *reinterpret_cast<const float4*>(&T[(size_t)node * DIN + col]);
            o = make_float4((a0.x + a1.x + dn * sv.x) * dn,
                            (a0.y + a1.y + dn * sv.y) * dn,
                            (a0.z + a1.z + dn * sv.z) * dn,
                            (a0.w + a1.w + dn * sv.w) * dn);
        }
        *reinterpret_cast<float4*>(&xs[r * XP + col]) = o;
    }
    __syncthreads();

    // ---- gemm + bn3 + elu + W4 dot phase ------------------------------------
    const int ox = tid % OX;             // == lane
    const int r0 = (tid / OX) * R;

    float4 acc[R];
#pragma unroll
    for (int j = 0; j < R; ++j) acc[j] = make_float4(0.f, 0.f, 0.f, 0.f);

#pragma unroll 4
    for (int k = 0; k < DIN; ++k) {
        float4 w = *reinterpret_cast<const float4*>(&Ws[k * DOUT + ox * 4]);
#pragma unroll
        for (int j = 0; j < R; ++j) {
            float xv = xs[(r0 + j) * XP + k];
            acc[j].x += xv * w.x; acc[j].y += xv * w.y;
            acc[j].z += xv * w.z; acc[j].w += xv * w.w;
        }
    }

    const float4 s4 = *reinterpret_cast<const float4*>(&sh_scale[ox * 4]);
    const float4 h4 = *reinterpret_cast<const float4*>(&sh_shift[ox * 4]);
    const float4 w4 = *reinterpret_cast<const float4*>(&w4s[ox * 4]);
#pragma unroll
    for (int j = 0; j < R; ++j) {
        float4 o = acc[j];
        o.x = o.x * s4.x + h4.x; o.y = o.y * s4.y + h4.y;
        o.z = o.z * s4.z + h4.z; o.w = o.w * s4.w + h4.w;
        o.x = (o.x > 0.f) ? o.x : expm1f(o.x);
        o.y = (o.y > 0.f) ? o.y : expm1f(o.y);
        o.z = (o.z > 0.f) ? o.z : expm1f(o.z);
        o.w = (o.w > 0.f) ? o.w : expm1f(o.w);
        float p = o.x * w4.x + o.y * w4.y + o.z * w4.z + o.w * w4.w;
#pragma unroll
        for (int sh = 16; sh > 0; sh >>= 1)
            p += __shfl_xor_sync(0xffffffffu, p, sh);
        int node = base + r0 + j;
        if (ox == 0 && node < NN) t4[node] = p;
    }
}

__global__ void __launch_bounds__(256) k_gather1_final(const float* __restrict__ t4,
                                const int* __restrict__ rowptr,
                                const int2* __restrict__ edges,
                                const float* __restrict__ dis,
                                const float* __restrict__ b4,
                                float* __restrict__ out) {
    const int warp = (blockIdx.x * blockDim.x + threadIdx.x) >> 5;
    const int lane = threadIdx.x & 31;
    if (warp >= NN) return;
    const int node = warp;
    const int beg = rowptr[node], end = rowptr[node + 1];
    float acc = 0.0f;
    for (int i = beg + lane; i < end; i += 32) {
        int2 e = edges[i];
        acc += __int_as_float(e.y) * t4[e.x];
    }
#pragma unroll
    for (int o = 16; o > 0; o >>= 1) acc += __shfl_xor_sync(0xffffffffu, acc, o);
    if (lane == 0) {
        float dn = dis[node];
        float x = (acc + dn * t4[node]) * dn + b4[0];
        x = (x > 0.0f) ? x : expm1f(x);
        out[node] = 1.0f / (1.0f + expf(-x));
    }
}

// ---------------- launch -----------------------------------------------------
extern "C" void kernel_launch(void* const* d_in, const int* in_sizes, int n_in,
                              void* d_out, int out_size) {
    const float* x   = (const float*)d_in[0];
    const int*   src = (const int*)  d_in[1];
    const int*   dst = (const int*)  d_in[2];
    const float* W1 = (const float*)d_in[3];  const float* b1 = (const float*)d_in[4];
    const float* W2 = (const float*)d_in[5];  const float* b2 = (const float*)d_in[6];
    const float* W3 = (const float*)d_in[7];  const float* b3 = (const float*)d_in[8];
    const float* W4 = (const float*)d_in[9];  const float* b4 = (const float*)d_in[10];
    const float* g1 = (const float*)d_in[11]; const float* be1 = (const float*)d_in[12];
    const float* m1 = (const float*)d_in[13]; const float* v1  = (const float*)d_in[14];
    const float* g2 = (const float*)d_in[15]; const float* be2 = (const float*)d_in[16];
    const float* m2 = (const float*)d_in[17]; const float* v2  = (const float*)d_in[18];
    const float* g3 = (const float*)d_in[19]; const float* be3 = (const float*)d_in[20];
    const float* m3 = (const float*)d_in[21]; const float* v3  = (const float*)d_in[22];
    float* out = (float*)d_out;

    void *pcnt, *ppart, *prp, *pcur, *pdis, *pedge, *pT, *pA, *pt4;
    cudaGetSymbolAddress(&pcnt, g_cnt);
    cudaGetSymbolAddress(&ppart, g_part);
    cudaGetSymbolAddress(&prp,  g_rowptr);
    cudaGetSymbolAddress(&pcur, g_cursor);
    cudaGetSymbolAddress(&pdis, g_dis);
    cudaGetSymbolAddress(&pedge, g_edge);
    cudaGetSymbolAddress(&pT, g_T);
    cudaGetSymbolAddress(&pA, g_A);
    cudaGetSymbolAddress(&pt4, g_t4);
    int* cnt = (int*)pcnt; int* part = (int*)ppart;
    int* rowptr = (int*)prp; int* cursor = (int*)pcur;
    float* dis = (float*)pdis;
    int2* edges = (int2*)pedge;
    float* T = (float*)pT; float* A = (float*)pA;
    float* t4 = (float*)pt4;

    const int TB = 256;
    const int gE = (NE + TB - 1) / TB;
    const int gW = (NN + 7) / 8;                 // warp-per-node kernels
    const int gW4 = (NN + 4 * 8 - 1) / (4 * 8);  // G=4 sub-warp gather (dim 32)
    const int NBLK = (NN + 1023) / 1024;         // 98 scan blocks

    const int SM1 = 128*32*4 + 64*129*4;   // 49408 bytes dynamic smem for gemm1
    cudaFuncSetAttribute((const void*)k_gemm1_count,
                         cudaFuncAttributeMaxDynamicSharedMemorySize, SM1);

    // (1) gemm1 (x@W1 -> T) fused with degree count
    k_gemm1_count<<<(NN + 63) / 64, TB, SM1>>>(x, W1, T, dst, cnt);
    // (2,3) multi-block scan
    k_scan_part<<<NBLK, 1024>>>(cnt, part);
    k_scan_apply<<<NBLK, 1024>>>(cnt, part, rowptr, cursor, dis);
    // (4) permute  [profiled control]
    k_permute<<<gE, TB>>>(src, dst, dis, cursor, edges);

    // layer 1 gather dim32 (G=4) + bias+bn1+elu -> H2 (A)
    k_gatherG<32, 4, true><<<gW4, TB>>>(T, rowptr, edges, dis, b1, g1, be1, m1, v1, A);

    // layer 2 fused: aggregate H2 (dim32) into smem, gemm 32->64 + bn2+elu -> T
    k_agg_gemm2<<<(NN + 63) / 64, TB>>>(A, rowptr, edges, dis,
                                        W2, b2, g2, be2, m2, v2, T);

    // layer 3+4a fused: aggregate H3 (dim64) into smem, gemm3 + bn3+elu + W4 dot -> t4
    k_agg_gemm3_dot<<<(NN + 31) / 32, TB>>>(T, rowptr, edges, dis,
                                            W3, b3, g3, be3, m3, v3, W4, t4);

    // layer 4 final gather + elu + sigmoid
    k_gather1_final<<<gW, TB>>>(t4, rowptr, edges, dis, b4, out);
}